// round 4
// baseline (speedup 1.0000x reference)
#include <cuda_runtime.h>
#include <cstdint>
#include <math.h>

#define BB 16
#define HH 768
#define WW 768
#define NPIX (HH*WW)
#define TOPK 100
#define NP 4
#define NPATCH (BB*NP)   // 64
#define PS 64            // patch size

// ---------------- scratch (static device globals) ----------------
__device__ float g_mask[BB*NPIX];
__device__ float g_tmp[BB*NPIX];
__device__ unsigned g_hist[BB][256];
__device__ unsigned g_prefix[BB];
__device__ int g_K[BB];
__device__ int g_cntA[BB];
__device__ int g_cntB[BB];
__device__ unsigned long long g_listA[BB][128];
__device__ int g_listB[BB][16384];
__device__ int g_py[NPATCH], g_px[NPATCH];
__device__ float g_patches[NPATCH*3*PS*PS];
__device__ float g_act1[NPATCH*64*32*32];
__device__ float g_act2[NPATCH*128*16*16];
__device__ float g_act3[NPATCH*256*8*8];
__device__ float g_act4[NPATCH*512*4*4];
__device__ float g_part[4194304];
__device__ float g_bnscale[512], g_bnshift[512];

// ---------------- detector fused into 15-tap horizontal pool ---------------
__global__ void hpool_det_kernel(const float* __restrict__ src) {
    __shared__ float row[WW + 14];
    int y = blockIdx.x, b = blockIdx.y;
    const float* sb = src + ((size_t)b*3*HH + y)*WW;
    for (int i = threadIdx.x; i < WW + 14; i += blockDim.x) {
        int x = i - 7;
        float m = 0.f;
        if (x >= 0 && x < WW) {
            float r  = (sb[x]               + 1.f)*0.5f;
            float gg = (sb[(size_t)HH*WW + x]   + 1.f)*0.5f;
            float bl = (sb[(size_t)2*HH*WW + x] + 1.f)*0.5f;
            float br = 0.299f*r + 0.587f*gg + 0.114f*bl;
            float bm = 1.f/(1.f + expf(-20.f*(br - 0.65f)));
            float mx = fmaxf(r, fmaxf(gg, bl));
            float mn = fminf(r, fminf(gg, bl));
            float ls = 1.f/(1.f + expf(-20.f*(0.15f - (mx - mn))));
            m = bm*ls;
        }
        row[i] = m;
    }
    __syncthreads();
    float* op = g_tmp + ((size_t)b*HH + y)*WW;
    for (int x = threadIdx.x; x < WW; x += blockDim.x) {
        float s = 0.f;
        #pragma unroll
        for (int d = 0; d < 15; d++) s += row[x + d];
        op[x] = s;
    }
}

// ---------------- 15-tap vertical sum + /225 -> g_mask --------
__global__ void vpool_kernel() {
    __shared__ float tile[78][32];
    int c0 = blockIdx.x*32, r0 = blockIdx.y*64, b = blockIdx.z;
    const float* ip = g_tmp + (size_t)b*NPIX;
    for (int i = threadIdx.x; i < 78*32; i += blockDim.x) {
        int r = i >> 5, c = i & 31;
        int y = r0 + r - 7;
        tile[r][c] = (y >= 0 && y < HH) ? ip[(size_t)y*WW + c0 + c] : 0.f;
    }
    __syncthreads();
    float* op = g_mask + (size_t)b*NPIX;
    int c = threadIdx.x & 31;
    for (int rr = threadIdx.x >> 5; rr < 64; rr += blockDim.x >> 5) {
        float s = 0.f;
        #pragma unroll
        for (int d = 0; d < 15; d++) s += tile[rr + d][c];
        op[(size_t)(r0 + rr)*WW + c0 + c] = s / 225.0f;
    }
}

// ---------------- exact top-100 via MSB radix select (grid-wide) ----------
__global__ void topk_init_kernel() {
    int t = threadIdx.x;
    if (t < BB) { g_prefix[t] = 0u; g_K[t] = TOPK; g_cntA[t] = 0; g_cntB[t] = 0; }
    for (int i = t; i < BB*256; i += blockDim.x) ((unsigned*)g_hist)[i] = 0u;
}

__global__ void topk_hist_kernel(int digit) {
    int b = blockIdx.y;
    __shared__ unsigned sh[256];
    for (int i = threadIdx.x; i < 256; i += blockDim.x) sh[i] = 0u;
    __syncthreads();
    unsigned pref  = g_prefix[b];
    unsigned hmask = (digit == 3) ? 0u : (0xFFFFFFFFu << ((digit + 1)*8));
    const float* wp = g_mask + (size_t)b*NPIX;
    for (int i = blockIdx.x*blockDim.x + threadIdx.x; i < NPIX; i += gridDim.x*blockDim.x) {
        unsigned key = __float_as_uint(wp[i]);
        if ((key & hmask) == (pref & hmask))
            atomicAdd(&sh[(key >> (digit*8)) & 255u], 1u);
    }
    __syncthreads();
    for (int i = threadIdx.x; i < 256; i += blockDim.x)
        if (sh[i]) atomicAdd(&g_hist[b][i], sh[i]);
}

__global__ void topk_resolve_kernel(int digit) {
    int b = threadIdx.x;
    if (b < BB) {
        int K = g_K[b];
        unsigned acc = 0;
        int bin = 0;
        for (int j = 255; j >= 0; j--) {
            unsigned c = g_hist[b][j];
            if (acc + c >= (unsigned)K) { bin = j; break; }
            acc += c;
        }
        g_prefix[b] |= ((unsigned)bin) << (digit*8);
        g_K[b] = K - (int)acc;
    }
    __syncthreads();
    for (int i = threadIdx.x; i < BB*256; i += blockDim.x) ((unsigned*)g_hist)[i] = 0u;
}

__global__ void topk_collect_kernel() {
    int b = blockIdx.y;
    unsigned T = g_prefix[b];
    const float* wp = g_mask + (size_t)b*NPIX;
    for (int i = blockIdx.x*blockDim.x + threadIdx.x; i < NPIX; i += gridDim.x*blockDim.x) {
        unsigned key = __float_as_uint(wp[i]);
        if (key > T) {
            int p = atomicAdd(&g_cntA[b], 1);
            if (p < 128)
                g_listA[b][p] = ((unsigned long long)key << 32) | (unsigned)(0xFFFFFFFFu - (unsigned)i);
        } else if (key == T) {
            int p = atomicAdd(&g_cntB[b], 1);
            if (p < 16384) g_listB[b][p] = i;
        }
    }
}

// final sort/fill + patch coords fused
__global__ void topk_final_kernel(const int* __restrict__ rand_sel) {
    int b = blockIdx.x;
    int tid = threadIdx.x;                // 128 threads
    __shared__ unsigned long long A[128];
    __shared__ int stop[TOPK];
    int G = g_cntA[b]; if (G > 99) G = 99;
    if (tid == 0) {
        for (int i = 0; i < G; i++) A[i] = g_listA[b][i];
        for (int i = 1; i < G; i++) {     // insertion sort, descending
            unsigned long long v = A[i]; int j = i - 1;
            while (j >= 0 && A[j] < v) { A[j+1] = A[j]; j--; }
            A[j+1] = v;
        }
        for (int i = 0; i < G; i++)
            stop[i] = (int)(0xFFFFFFFFu - (unsigned)(A[i] & 0xFFFFFFFFu));
    }
    __syncthreads();
    int m  = TOPK - G;
    int nB = min(g_cntB[b], 16384);
    __shared__ int smin[128];
    for (int k = 0; k < m; k++) {
        int lmin = 0x7FFFFFFF;
        for (int i = tid; i < nB; i += 128) { int v = g_listB[b][i]; if (v < lmin) lmin = v; }
        smin[tid] = lmin; __syncthreads();
        for (int s = 64; s > 0; s >>= 1) { if (tid < s) smin[tid] = min(smin[tid], smin[tid + s]); __syncthreads(); }
        int mv = smin[0];
        __syncthreads();
        if (tid == 0) stop[G + k] = mv;
        for (int i = tid; i < nB; i += 128) if (g_listB[b][i] == mv) g_listB[b][i] = 0x7FFFFFFF;
        __syncthreads();
    }
    if (tid < NP) {
        int r = rand_sel[b*NP + tid];
        int sel = stop[r];
        int y = sel / WW - PS/2; y = max(0, min(y, HH - PS));
        int x = sel % WW - PS/2; x = max(0, min(x, WW - PS));
        g_py[b*NP + tid] = y; g_px[b*NP + tid] = x;
    }
}

// ---------------- patch gather ----------------
__global__ void gather_kernel(const float* __restrict__ pred) {
    int idx = blockIdx.x*blockDim.x + threadIdx.x;
    const int total = NPATCH*3*PS*PS;
    if (idx >= total) return;
    int j = idx & 63; int t = idx >> 6;
    int i = t & 63;   t >>= 6;
    int c = t % 3;    int p = t / 3;
    int b = p >> 2;
    g_patches[idx] = pred[(((size_t)b*3 + c)*HH + g_py[p] + i)*WW + g_px[p] + j];
}

// ---------------- conv1: implicit GEMM 64x64, plain FFMA, K=48 ------------
__global__ __launch_bounds__(256) void conv1_kernel(
        const float* __restrict__ in, const float* __restrict__ w,
        const float* __restrict__ bias, float* __restrict__ out) {
    constexpr int IC = 3, LOG_OW = 5, OW = 32, OHW = OW*OW, IW = 64, IH = 64, K = 48;
    __shared__ __align__(16) float As[2][16][68];
    __shared__ __align__(16) float Bs[2][16][68];
    const int tid = threadIdx.x;
    const int m0  = blockIdx.x << 6;

    const int lm = tid >> 2;
    const int kq = (tid & 3) << 2;
    const int am   = m0 + lm;
    const int nimg = am >> (2*LOG_OW);
    const int arem = am & (OHW-1);
    const int ih0  = ((arem >> LOG_OW) << 1) - 1;
    const int iw0  = ((arem & (OW-1)) << 1) - 1;
    const float* ibase = in + (size_t)nimg*IC*IH*IW;

    const int boc = tid >> 2;
    const int bkq = (tid & 3) << 2;

    const int tm = (tid >> 4) << 2;
    const int tn = (tid & 15) << 2;

    float acc[4][4] = {};
    float pa[4]; float4 pbv;

    auto loadA = [&](int kc) {
        int k  = kc + kq;
        int ic = k >> 4;
        int ih = ih0 + ((k >> 2) & 3);
        const float* rp = ibase + ((size_t)ic*IH + ih)*IW;
        bool rowok = (unsigned)ih < (unsigned)IH;
        #pragma unroll
        for (int j = 0; j < 4; j++) {
            int iw = iw0 + j;
            pa[j] = (rowok && (unsigned)iw < (unsigned)IW) ? __ldg(rp + iw) : 0.f;
        }
    };
    auto loadB = [&](int kc) {
        pbv = *(const float4*)&w[(size_t)boc*K + kc + bkq];
    };
    auto stsA = [&](int buf) {
        #pragma unroll
        for (int j = 0; j < 4; j++) As[buf][kq+j][lm] = pa[j];
    };
    auto stsB = [&](int buf) {
        Bs[buf][bkq+0][boc] = pbv.x; Bs[buf][bkq+1][boc] = pbv.y;
        Bs[buf][bkq+2][boc] = pbv.z; Bs[buf][bkq+3][boc] = pbv.w;
    };

    loadA(0); loadB(0); stsA(0); stsB(0); __syncthreads();
    const int nch = K >> 4;
    for (int ch = 0; ch < nch; ch++) {
        int cur = ch & 1;
        if (ch + 1 < nch) { loadA((ch+1) << 4); loadB((ch+1) << 4); }
        #pragma unroll
        for (int k = 0; k < 16; k++) {
            float4 a = *(const float4*)&As[cur][k][tm];
            float4 b = *(const float4*)&Bs[cur][k][tn];
            acc[0][0] += a.x*b.x; acc[0][1] += a.x*b.y; acc[0][2] += a.x*b.z; acc[0][3] += a.x*b.w;
            acc[1][0] += a.y*b.x; acc[1][1] += a.y*b.y; acc[1][2] += a.y*b.z; acc[1][3] += a.y*b.w;
            acc[2][0] += a.z*b.x; acc[2][1] += a.z*b.y; acc[2][2] += a.z*b.z; acc[2][3] += a.z*b.w;
            acc[3][0] += a.w*b.x; acc[3][1] += a.w*b.y; acc[3][2] += a.w*b.z; acc[3][3] += a.w*b.w;
        }
        if (ch + 1 < nch) { stsA(cur ^ 1); stsB(cur ^ 1); __syncthreads(); }
    }

    const float4 bv = *(const float4*)&bias[tn];
    float b4[4] = {bv.x, bv.y, bv.z, bv.w};
    #pragma unroll
    for (int i = 0; i < 4; i++) {
        int m    = m0 + tm + i;
        int ni   = m >> (2*LOG_OW);
        int rem  = m & (OHW-1);
        float* op = out + ((size_t)ni*64 + tn)*OHW + rem;
        #pragma unroll
        for (int j = 0; j < 4; j++) {
            float v = acc[i][j] + b4[j];
            v = v > 0.f ? v : 0.2f*v;
            op[(size_t)j*OHW] = v;
        }
    }
}

// ---------------- conv2-4: implicit GEMM 64x128, f32x2 FMA, split-K -------
template<int IC, int LOG_OW, bool BNIN>
__global__ __launch_bounds__(256) void conv_gemm2_kernel(
        const float* __restrict__ in, const float* __restrict__ w,
        float* __restrict__ part, int K, int Kchunk) {
    constexpr int OW = 1 << LOG_OW, OHW = OW*OW, IW = 2*OW, IH = IW;
    __shared__ __align__(16) float As2[2][16][128];
    __shared__ __align__(16) float Bs[2][16][128];
    const int tid = threadIdx.x;
    const int m0  = blockIdx.x << 6;
    const int n0  = blockIdx.y << 7;
    const int NN  = gridDim.y << 7;
    const int MM  = gridDim.x << 6;
    const int k0  = blockIdx.z * Kchunk;
    float* pout = part + (size_t)blockIdx.z * MM * NN;

    const int lm = tid & 63;
    const int kq = (tid >> 6) << 2;
    const int am   = m0 + lm;
    const int nimg = am >> (2*LOG_OW);
    const int arem = am & (OHW-1);
    const int ih0  = ((arem >> LOG_OW) << 1) - 1;
    const int iw0  = ((arem & (OW-1)) << 1) - 1;
    const float* ibase = in + (size_t)nimg*IC*IH*IW;

    const int boc = tid >> 1;
    const int bk8 = (tid & 1) << 3;
    const float* wrow = w + (size_t)(n0 + boc)*K + bk8;

    const int tm = (tid >> 4) << 2;
    const int tn = (tid & 15) << 3;

    unsigned long long acc[4][4];
    #pragma unroll
    for (int i = 0; i < 4; i++)
        #pragma unroll
        for (int j = 0; j < 4; j++) acc[i][j] = 0ull;

    float pa[4]; float4 pb0, pb1;

    auto loadA = [&](int kc) {
        int k  = kc + kq;
        int ic = k >> 4;
        int ih = ih0 + ((k >> 2) & 3);
        const float* rp = ibase + ((size_t)ic*IH + ih)*IW;
        bool rowok = (unsigned)ih < (unsigned)IH;
        float sc = 0.f, sh = 0.f;
        if (BNIN) { sc = g_bnscale[ic]; sh = g_bnshift[ic]; }
        #pragma unroll
        for (int j = 0; j < 4; j++) {
            int iw = iw0 + j;
            float v = 0.f;
            if (rowok && (unsigned)iw < (unsigned)IW) {
                v = __ldg(rp + iw);
                if (BNIN) { v = v*sc + sh; v = v > 0.f ? v : 0.2f*v; }
            }
            pa[j] = v;
        }
    };
    auto loadB = [&](int kc) {
        pb0 = *(const float4*)(wrow + kc);
        pb1 = *(const float4*)(wrow + kc + 4);
    };
    auto stsA = [&](int buf) {
        #pragma unroll
        for (int j = 0; j < 4; j++)
            *(float2*)&As2[buf][kq+j][2*lm] = make_float2(pa[j], pa[j]);
    };
    auto stsB = [&](int buf) {
        Bs[buf][bk8+0][boc] = pb0.x; Bs[buf][bk8+1][boc] = pb0.y;
        Bs[buf][bk8+2][boc] = pb0.z; Bs[buf][bk8+3][boc] = pb0.w;
        Bs[buf][bk8+4][boc] = pb1.x; Bs[buf][bk8+5][boc] = pb1.y;
        Bs[buf][bk8+6][boc] = pb1.z; Bs[buf][bk8+7][boc] = pb1.w;
    };

    loadA(k0); loadB(k0); stsA(0); stsB(0); __syncthreads();
    const int nch = Kchunk >> 4;
    for (int ch = 0; ch < nch; ch++) {
        int cur = ch & 1;
        if (ch + 1 < nch) { loadA(k0 + ((ch+1) << 4)); loadB(k0 + ((ch+1) << 4)); }
        #pragma unroll
        for (int k = 0; k < 16; k++) {
            double2 a01 = *(const double2*)&As2[cur][k][2*tm];
            double2 a23 = *(const double2*)&As2[cur][k][2*tm + 4];
            double2 b01 = *(const double2*)&Bs[cur][k][tn];
            double2 b23 = *(const double2*)&Bs[cur][k][tn + 4];
            unsigned long long aa0 = __double_as_longlong(a01.x);
            unsigned long long aa1 = __double_as_longlong(a01.y);
            unsigned long long aa2 = __double_as_longlong(a23.x);
            unsigned long long aa3 = __double_as_longlong(a23.y);
            unsigned long long bb0 = __double_as_longlong(b01.x);
            unsigned long long bb1 = __double_as_longlong(b01.y);
            unsigned long long bb2 = __double_as_longlong(b23.x);
            unsigned long long bb3 = __double_as_longlong(b23.y);
            asm("fma.rn.f32x2 %0, %1, %2, %0;" : "+l"(acc[0][0]) : "l"(aa0), "l"(bb0));
            asm("fma.rn.f32x2 %0, %1, %2, %0;" : "+l"(acc[0][1]) : "l"(aa0), "l"(bb1));
            asm("fma.rn.f32x2 %0, %1, %2, %0;" : "+l"(acc[0][2]) : "l"(aa0), "l"(bb2));
            asm("fma.rn.f32x2 %0, %1, %2, %0;" : "+l"(acc[0][3]) : "l"(aa0), "l"(bb3));
            asm("fma.rn.f32x2 %0, %1, %2, %0;" : "+l"(acc[1][0]) : "l"(aa1), "l"(bb0));
            asm("fma.rn.f32x2 %0, %1, %2, %0;" : "+l"(acc[1][1]) : "l"(aa1), "l"(bb1));
            asm("fma.rn.f32x2 %0, %1, %2, %0;" : "+l"(acc[1][2]) : "l"(aa1), "l"(bb2));
            asm("fma.rn.f32x2 %0, %1, %2, %0;" : "+l"(acc[1][3]) : "l"(aa1), "l"(bb3));
            asm("fma.rn.f32x2 %0, %1, %2, %0;" : "+l"(acc[2][0]) : "l"(aa2), "l"(bb0));
            asm("fma.rn.f32x2 %0, %1, %2, %0;" : "+l"(acc[2][1]) : "l"(aa2), "l"(bb1));
            asm("fma.rn.f32x2 %0, %1, %2, %0;" : "+l"(acc[2][2]) : "l"(aa2), "l"(bb2));
            asm("fma.rn.f32x2 %0, %1, %2, %0;" : "+l"(acc[2][3]) : "l"(aa2), "l"(bb3));
            asm("fma.rn.f32x2 %0, %1, %2, %0;" : "+l"(acc[3][0]) : "l"(aa3), "l"(bb0));
            asm("fma.rn.f32x2 %0, %1, %2, %0;" : "+l"(acc[3][1]) : "l"(aa3), "l"(bb1));
            asm("fma.rn.f32x2 %0, %1, %2, %0;" : "+l"(acc[3][2]) : "l"(aa3), "l"(bb2));
            asm("fma.rn.f32x2 %0, %1, %2, %0;" : "+l"(acc[3][3]) : "l"(aa3), "l"(bb3));
        }
        if (ch + 1 < nch) { stsA(cur ^ 1); stsB(cur ^ 1); __syncthreads(); }
    }

    #pragma unroll
    for (int i = 0; i < 4; i++) {
        int m = m0 + tm + i;
        unsigned long long* op = (unsigned long long*)(pout + (size_t)m*NN + n0 + tn);
        op[0] = acc[i][0]; op[1] = acc[i][1]; op[2] = acc[i][2]; op[3] = acc[i][3];
    }
}

// ---------------- split-K reduce + bias -> NCHW ----------------
__global__ void redk_kernel(const float* __restrict__ part, const float* __restrict__ bias,
                            float* __restrict__ out, int MN, int log_nn, int KS, int log_ohw) {
    int NNm = (1 << log_nn) - 1;
    int OHWm = (1 << log_ohw) - 1;
    for (int idx = blockIdx.x*blockDim.x + threadIdx.x; idx < MN; idx += gridDim.x*blockDim.x) {
        int m = idx >> log_nn, n = idx & NNm;
        float s = 0.f;
        for (int z = 0; z < KS; z++) s += part[(size_t)z*MN + idx];
        s += bias[n];
        int ni = m >> log_ohw, rem = m & OHWm;
        out[((((size_t)ni << log_nn) + n) << log_ohw) + rem] = s;
    }
}

// ---------------- batchnorm stats (double accum) ----------------
__global__ void bn_reduce_kernel(const float* __restrict__ x, const float* __restrict__ g,
                                 const float* __restrict__ be, int N, int C, int S) {
    int c = blockIdx.x;
    double s = 0.0, s2 = 0.0;
    int M = N*S;
    for (int j = threadIdx.x; j < M; j += blockDim.x) {
        int n = j / S, sp = j % S;
        float v = x[((size_t)n*C + c)*S + sp];
        s += (double)v; s2 += (double)v*(double)v;
    }
    __shared__ double sh[256], sh2[256];
    sh[threadIdx.x] = s; sh2[threadIdx.x] = s2; __syncthreads();
    for (int st = 128; st > 0; st >>= 1) {
        if (threadIdx.x < st) { sh[threadIdx.x] += sh[threadIdx.x+st]; sh2[threadIdx.x] += sh2[threadIdx.x+st]; }
        __syncthreads();
    }
    if (threadIdx.x == 0) {
        double mean = sh[0] / M;
        double var  = sh2[0] / M - mean*mean;
        double isd  = 1.0 / sqrt(var + 1e-5);
        float sc = (float)((double)g[c] * isd);
        g_bnscale[c] = sc;
        g_bnshift[c] = be[c] - (float)(mean * (double)sc);
    }
}

// ---------------- head: bn4+lrelu+conv5 dot+softplus+mean ----------------
__global__ void head_kernel(const float* __restrict__ a4, const float* __restrict__ w5,
                            const float* __restrict__ b5, float* __restrict__ out) {
    int tid = threadIdx.x;            // 512
    int lane = tid & 31, warp = tid >> 5;   // 16 warps
    __shared__ float slog[64];
    for (int p = warp; p < NPATCH; p += 16) {
        const float* ap = a4 + (size_t)p*8192;
        float s = 0.f;
        for (int i = lane; i < 8192; i += 32) {
            int c = i >> 4;
            float v = ap[i]*g_bnscale[c] + g_bnshift[c];
            v = v > 0.f ? v : 0.2f*v;
            s += v * w5[i];
        }
        #pragma unroll
        for (int d = 16; d > 0; d >>= 1) s += __shfl_xor_sync(0xFFFFFFFFu, s, d);
        if (lane == 0) slog[p] = s + b5[0];
    }
    __syncthreads();
    if (tid < 64) {
        float x = -slog[tid];
        slog[tid] = fmaxf(x, 0.f) + log1pf(expf(-fabsf(x)));
    }
    __syncthreads();
    if (tid < 32) {
        float v = slog[tid] + slog[tid + 32];
        #pragma unroll
        for (int d = 16; d > 0; d >>= 1) v += __shfl_xor_sync(0xFFFFFFFFu, v, d);
        if (tid == 0) out[0] = v / 64.f;
    }
}

// ---------------- launcher ----------------
extern "C" void kernel_launch(void* const* d_in, const int* in_sizes, int n_in,
                              void* d_out, int out_size) {
    const float* pred     = (const float*)d_in[0];
    const float* source   = (const float*)d_in[1];
    const int*   rand_sel = (const int*)d_in[2];
    const float* w1 = (const float*)d_in[3];  const float* b1 = (const float*)d_in[4];
    const float* w2 = (const float*)d_in[5];  const float* b2 = (const float*)d_in[6];
    const float* g2 = (const float*)d_in[7];  const float* be2= (const float*)d_in[8];
    const float* w3 = (const float*)d_in[9];  const float* b3 = (const float*)d_in[10];
    const float* g3 = (const float*)d_in[11]; const float* be3= (const float*)d_in[12];
    const float* w4 = (const float*)d_in[13]; const float* b4 = (const float*)d_in[14];
    const float* g4 = (const float*)d_in[15]; const float* be4= (const float*)d_in[16];
    const float* w5 = (const float*)d_in[17]; const float* b5 = (const float*)d_in[18];
    float* out = (float*)d_out;

    float *patches, *a1, *a2, *a3, *a4, *part;
    cudaGetSymbolAddress((void**)&patches, g_patches);
    cudaGetSymbolAddress((void**)&a1, g_act1);
    cudaGetSymbolAddress((void**)&a2, g_act2);
    cudaGetSymbolAddress((void**)&a3, g_act3);
    cudaGetSymbolAddress((void**)&a4, g_act4);
    cudaGetSymbolAddress((void**)&part, g_part);

    // detector + pools
    hpool_det_kernel<<<dim3(HH, BB), 256>>>(source);
    vpool_kernel<<<dim3(WW/32, HH/64, BB), 256>>>();
    // exact per-image top-100 (grid-wide radix select)
    topk_init_kernel<<<1, 256>>>();
    for (int d = 3; d >= 0; d--) {
        topk_hist_kernel<<<dim3(48, BB), 256>>>(d);
        topk_resolve_kernel<<<1, 256>>>(d);
    }
    topk_collect_kernel<<<dim3(48, BB), 256>>>();
    topk_final_kernel<<<BB, 128>>>(rand_sel);
    // patch gather
    gather_kernel<<<(NPATCH*3*PS*PS + 255)/256, 256>>>(pred);
    // conv1 (64x64 tiles, bias+lrelu fused)
    conv1_kernel<<<1024, 256>>>(patches, w1, b1, a1);
    // conv2: M=16384, N=128, K=1024, split-K=2
    conv_gemm2_kernel<64, 4, false><<<dim3(256, 1, 2), 256>>>(a1, w2, part, 1024, 512);
    redk_kernel<<<2048, 256>>>(part, b2, a2, 16384*128, 7, 2, 8);
    bn_reduce_kernel<<<128, 256>>>(a2, g2, be2, NPATCH, 128, 16*16);
    // conv3: M=4096, N=256, K=2048, split-K=4, BN2+lrelu fused into input
    conv_gemm2_kernel<128, 3, true><<<dim3(64, 2, 4), 256>>>(a2, w3, part, 2048, 512);
    redk_kernel<<<1024, 256>>>(part, b3, a3, 4096*256, 8, 4, 6);
    bn_reduce_kernel<<<256, 256>>>(a3, g3, be3, NPATCH, 256, 8*8);
    // conv4: M=1024, N=512, K=4096, split-K=8, BN3+lrelu fused into input
    conv_gemm2_kernel<256, 2, true><<<dim3(16, 4, 8), 256>>>(a3, w4, part, 4096, 512);
    redk_kernel<<<512, 256>>>(part, b4, a4, 1024*512, 9, 8, 4);
    bn_reduce_kernel<<<512, 256>>>(a4, g4, be4, NPATCH, 512, 4*4);
    // head: bn4+lrelu+conv5+softplus+mean
    head_kernel<<<1, 512>>>(a4, w5, b5, out);
}

// round 5
// speedup vs baseline: 1.2353x; 1.2353x over previous
#include <cuda_runtime.h>
#include <cstdint>
#include <math.h>

#define BB 16
#define HH 768
#define WW 768
#define NPIX (HH*WW)
#define TOPK 100
#define NP 4
#define NPATCH (BB*NP)   // 64
#define PS 64            // patch size

// ---------------- scratch (static device globals) ----------------
__device__ float g_mask[BB*NPIX];
__device__ float g_tmp[BB*NPIX];
__device__ int g_listB[BB][32768];
__device__ int g_py[NPATCH], g_px[NPATCH];
__device__ float g_patches[NPATCH*3*PS*PS];
__device__ float g_act1[NPATCH*64*32*32];
__device__ float g_act2[NPATCH*128*16*16];
__device__ float g_act3[NPATCH*256*8*8];
__device__ float g_act4[NPATCH*512*4*4];
__device__ float g_part[4194304];
__device__ float g_bnscale[512], g_bnshift[512];

// ---------------- detector fused into 15-tap horizontal pool ---------------
__global__ void hpool_det_kernel(const float* __restrict__ src) {
    __shared__ float row[WW + 14];
    int y = blockIdx.x, b = blockIdx.y;
    const float* sb = src + ((size_t)b*3*HH + y)*WW;
    for (int i = threadIdx.x; i < WW + 14; i += blockDim.x) {
        int x = i - 7;
        float m = 0.f;
        if (x >= 0 && x < WW) {
            float r  = (sb[x]               + 1.f)*0.5f;
            float gg = (sb[(size_t)HH*WW + x]   + 1.f)*0.5f;
            float bl = (sb[(size_t)2*HH*WW + x] + 1.f)*0.5f;
            float br = 0.299f*r + 0.587f*gg + 0.114f*bl;
            float bm = 1.f/(1.f + expf(-20.f*(br - 0.65f)));
            float mx = fmaxf(r, fmaxf(gg, bl));
            float mn = fminf(r, fminf(gg, bl));
            float ls = 1.f/(1.f + expf(-20.f*(0.15f - (mx - mn))));
            m = bm*ls;
        }
        row[i] = m;
    }
    __syncthreads();
    float* op = g_tmp + ((size_t)b*HH + y)*WW;
    for (int x = threadIdx.x; x < WW; x += blockDim.x) {
        float s = 0.f;
        #pragma unroll
        for (int d = 0; d < 15; d++) s += row[x + d];
        op[x] = s;
    }
}

// ---------------- 15-tap vertical sum + /225 -> g_mask --------
__global__ void vpool_kernel() {
    __shared__ float tile[78][32];
    int c0 = blockIdx.x*32, r0 = blockIdx.y*64, b = blockIdx.z;
    const float* ip = g_tmp + (size_t)b*NPIX;
    for (int i = threadIdx.x; i < 78*32; i += blockDim.x) {
        int r = i >> 5, c = i & 31;
        int y = r0 + r - 7;
        tile[r][c] = (y >= 0 && y < HH) ? ip[(size_t)y*WW + c0 + c] : 0.f;
    }
    __syncthreads();
    float* op = g_mask + (size_t)b*NPIX;
    int c = threadIdx.x & 31;
    for (int rr = threadIdx.x >> 5; rr < 64; rr += blockDim.x >> 5) {
        float s = 0.f;
        #pragma unroll
        for (int d = 0; d < 15; d++) s += tile[rr + d][c];
        op[(size_t)(r0 + rr)*WW + c0 + c] = s / 225.0f;
    }
}

// ---------------- fused exact top-100 + coords: one block per image -------
__global__ __launch_bounds__(1024) void topk_all_kernel(const int* __restrict__ rand_sel) {
    const int b = blockIdx.x, tid = threadIdx.x;
    __shared__ unsigned hist[256];
    __shared__ unsigned s_prefix;
    __shared__ int s_K, s_cntA, s_cntB, s_bin, s_above, s_m;
    __shared__ unsigned long long A[128];
    __shared__ int stop[TOPK];
    __shared__ int smin[32];
    const float4* wp4 = (const float4*)(g_mask + (size_t)b*NPIX);
    if (tid == 0) { s_prefix = 0u; s_K = TOPK; s_cntA = 0; s_cntB = 0; }
    __syncthreads();

    for (int digit = 3; digit >= 0; digit--) {
        for (int i = tid; i < 256; i += 1024) hist[i] = 0u;
        __syncthreads();
        unsigned pref  = s_prefix;
        int      K     = s_K;
        unsigned hmask = (digit == 3) ? 0u : (0xFFFFFFFFu << ((digit + 1)*8));
        for (int i = tid; i < NPIX/4; i += 1024) {
            float4 v = wp4[i];
            unsigned k0 = __float_as_uint(v.x), k1 = __float_as_uint(v.y);
            unsigned k2 = __float_as_uint(v.z), k3 = __float_as_uint(v.w);
            if ((k0 & hmask) == (pref & hmask)) atomicAdd(&hist[(k0 >> (digit*8)) & 255u], 1u);
            if ((k1 & hmask) == (pref & hmask)) atomicAdd(&hist[(k1 >> (digit*8)) & 255u], 1u);
            if ((k2 & hmask) == (pref & hmask)) atomicAdd(&hist[(k2 >> (digit*8)) & 255u], 1u);
            if ((k3 & hmask) == (pref & hmask)) atomicAdd(&hist[(k3 >> (digit*8)) & 255u], 1u);
        }
        __syncthreads();
        if (tid < 256) {
            unsigned above = 0;
            for (int j = tid + 1; j < 256; j++) above += hist[j];
            if ((int)above < K && (int)(above + hist[tid]) >= K) { s_bin = tid; s_above = (int)above; }
        }
        __syncthreads();
        if (tid == 0) {
            s_prefix |= ((unsigned)s_bin) << (digit*8);
            s_K = s_K - s_above;
        }
        __syncthreads();
    }

    // collect
    unsigned T = s_prefix;
    for (int i = tid; i < NPIX/4; i += 1024) {
        float4 v = wp4[i];
        unsigned kk[4] = {__float_as_uint(v.x), __float_as_uint(v.y),
                          __float_as_uint(v.z), __float_as_uint(v.w)};
        #pragma unroll
        for (int j = 0; j < 4; j++) {
            unsigned key = kk[j];
            int idx = 4*i + j;
            if (key > T) {
                int p = atomicAdd(&s_cntA, 1);
                if (p < 128)
                    A[p] = ((unsigned long long)key << 32) | (unsigned)(0xFFFFFFFFu - (unsigned)idx);
            } else if (key == T) {
                int p = atomicAdd(&s_cntB, 1);
                if (p < 32768) g_listB[b][p] = idx;
            }
        }
    }
    __syncthreads();

    int G = min(s_cntA, 99);
    if (tid < G) {
        unsigned long long v = A[tid];
        int r = 0;
        for (int j = 0; j < G; j++) r += (A[j] > v) ? 1 : 0;
        stop[r] = (int)(0xFFFFFFFFu - (unsigned)(v & 0xFFFFFFFFu));
    }
    __syncthreads();

    int m  = TOPK - G;
    int nB = min(s_cntB, 32768);
    int lane = tid & 31, warp = tid >> 5;
    for (int k = 0; k < m; k++) {
        int lmin = 0x7FFFFFFF;
        for (int i = tid; i < nB; i += 1024) { int v = g_listB[b][i]; if (v < lmin) lmin = v; }
        #pragma unroll
        for (int s = 16; s > 0; s >>= 1) lmin = min(lmin, __shfl_xor_sync(0xFFFFFFFFu, lmin, s));
        if (lane == 0) smin[warp] = lmin;
        __syncthreads();
        if (warp == 0) {
            int v = smin[lane];
            #pragma unroll
            for (int s = 16; s > 0; s >>= 1) v = min(v, __shfl_xor_sync(0xFFFFFFFFu, v, s));
            if (lane == 0) { s_m = v; stop[G + k] = v; }
        }
        __syncthreads();
        int mv = s_m;
        for (int i = tid; i < nB; i += 1024) if (g_listB[b][i] == mv) g_listB[b][i] = 0x7FFFFFFF;
        __syncthreads();
    }

    if (tid < NP) {
        int r = rand_sel[b*NP + tid];
        int sel = stop[r];
        int y = sel / WW - PS/2; y = max(0, min(y, HH - PS));
        int x = sel % WW - PS/2; x = max(0, min(x, WW - PS));
        g_py[b*NP + tid] = y; g_px[b*NP + tid] = x;
    }
}

// ---------------- patch gather ----------------
__global__ void gather_kernel(const float* __restrict__ pred) {
    int idx = blockIdx.x*blockDim.x + threadIdx.x;
    const int total = NPATCH*3*PS*PS;
    if (idx >= total) return;
    int j = idx & 63; int t = idx >> 6;
    int i = t & 63;   t >>= 6;
    int c = t % 3;    int p = t / 3;
    int b = p >> 2;
    g_patches[idx] = pred[(((size_t)b*3 + c)*HH + g_py[p] + i)*WW + g_px[p] + j];
}

// ---------------- conv1: implicit GEMM 64x64, plain FFMA, K=48 ------------
__global__ __launch_bounds__(256) void conv1_kernel(
        const float* __restrict__ in, const float* __restrict__ w,
        const float* __restrict__ bias, float* __restrict__ out) {
    constexpr int IC = 3, LOG_OW = 5, OW = 32, OHW = OW*OW, IW = 64, IH = 64, K = 48;
    __shared__ __align__(16) float As[2][16][68];
    __shared__ __align__(16) float Bs[2][16][68];
    const int tid = threadIdx.x;
    const int m0  = blockIdx.x << 6;

    const int lm = tid >> 2;
    const int kq = (tid & 3) << 2;
    const int am   = m0 + lm;
    const int nimg = am >> (2*LOG_OW);
    const int arem = am & (OHW-1);
    const int ih0  = ((arem >> LOG_OW) << 1) - 1;
    const int iw0  = ((arem & (OW-1)) << 1) - 1;
    const float* ibase = in + (size_t)nimg*IC*IH*IW;

    const int boc = tid >> 2;
    const int bkq = (tid & 3) << 2;

    const int tm = (tid >> 4) << 2;
    const int tn = (tid & 15) << 2;

    float acc[4][4] = {};
    float pa[4]; float4 pbv;

    auto loadA = [&](int kc) {
        int k  = kc + kq;
        int ic = k >> 4;
        int ih = ih0 + ((k >> 2) & 3);
        const float* rp = ibase + ((size_t)ic*IH + ih)*IW;
        bool rowok = (unsigned)ih < (unsigned)IH;
        #pragma unroll
        for (int j = 0; j < 4; j++) {
            int iw = iw0 + j;
            pa[j] = (rowok && (unsigned)iw < (unsigned)IW) ? __ldg(rp + iw) : 0.f;
        }
    };
    auto loadB = [&](int kc) {
        pbv = *(const float4*)&w[(size_t)boc*K + kc + bkq];
    };
    auto stsA = [&](int buf) {
        #pragma unroll
        for (int j = 0; j < 4; j++) As[buf][kq+j][lm] = pa[j];
    };
    auto stsB = [&](int buf) {
        Bs[buf][bkq+0][boc] = pbv.x; Bs[buf][bkq+1][boc] = pbv.y;
        Bs[buf][bkq+2][boc] = pbv.z; Bs[buf][bkq+3][boc] = pbv.w;
    };

    loadA(0); loadB(0); stsA(0); stsB(0); __syncthreads();
    const int nch = K >> 4;
    for (int ch = 0; ch < nch; ch++) {
        int cur = ch & 1;
        if (ch + 1 < nch) { loadA((ch+1) << 4); loadB((ch+1) << 4); }
        #pragma unroll
        for (int k = 0; k < 16; k++) {
            float4 a = *(const float4*)&As[cur][k][tm];
            float4 b = *(const float4*)&Bs[cur][k][tn];
            acc[0][0] += a.x*b.x; acc[0][1] += a.x*b.y; acc[0][2] += a.x*b.z; acc[0][3] += a.x*b.w;
            acc[1][0] += a.y*b.x; acc[1][1] += a.y*b.y; acc[1][2] += a.y*b.z; acc[1][3] += a.y*b.w;
            acc[2][0] += a.z*b.x; acc[2][1] += a.z*b.y; acc[2][2] += a.z*b.z; acc[2][3] += a.z*b.w;
            acc[3][0] += a.w*b.x; acc[3][1] += a.w*b.y; acc[3][2] += a.w*b.z; acc[3][3] += a.w*b.w;
        }
        if (ch + 1 < nch) { stsA(cur ^ 1); stsB(cur ^ 1); __syncthreads(); }
    }

    const float4 bv = *(const float4*)&bias[tn];
    float b4[4] = {bv.x, bv.y, bv.z, bv.w};
    #pragma unroll
    for (int i = 0; i < 4; i++) {
        int m    = m0 + tm + i;
        int ni   = m >> (2*LOG_OW);
        int rem  = m & (OHW-1);
        float* op = out + ((size_t)ni*64 + tn)*OHW + rem;
        #pragma unroll
        for (int j = 0; j < 4; j++) {
            float v = acc[i][j] + b4[j];
            v = v > 0.f ? v : 0.2f*v;
            op[(size_t)j*OHW] = v;
        }
    }
}

// ---------------- conv2-4: implicit GEMM 64x64, plain FFMA, split-K -------
// Writes partials to part[z][m][n] (no bias). Optional fused BN+lrelu on input.
// In-kernel weight transpose from w[OC][K] during B-tile load.
template<int IC, int LOG_OW, bool BNIN>
__global__ __launch_bounds__(256) void conv_gemm_kernel(
        const float* __restrict__ in, const float* __restrict__ w,
        float* __restrict__ part, int K, int Kchunk) {
    constexpr int OW = 1 << LOG_OW, OHW = OW*OW, IW = 2*OW, IH = IW;
    __shared__ __align__(16) float As[2][16][68];
    __shared__ __align__(16) float Bs[2][16][68];
    const int tid = threadIdx.x;
    const int m0  = blockIdx.x << 6;
    const int n0  = blockIdx.y << 6;
    const int NN  = gridDim.y << 6;
    const int MM  = gridDim.x << 6;
    const int k0  = blockIdx.z * Kchunk;
    float* pout = part + (size_t)blockIdx.z * MM * NN;

    const int lm = tid >> 2;
    const int kq = (tid & 3) << 2;
    const int am   = m0 + lm;
    const int nimg = am >> (2*LOG_OW);
    const int arem = am & (OHW-1);
    const int ih0  = ((arem >> LOG_OW) << 1) - 1;
    const int iw0  = ((arem & (OW-1)) << 1) - 1;
    const float* ibase = in + (size_t)nimg*IC*IH*IW;

    const int boc = tid >> 2;          // 0..63
    const int bkq = (tid & 3) << 2;    // 0,4,8,12
    const float* wrow = w + (size_t)(n0 + boc)*K + bkq;

    const int tm = (tid >> 4) << 2;
    const int tn = (tid & 15) << 2;

    float acc[4][4] = {};
    float pa[4]; float4 pbv;

    auto loadA = [&](int kc) {
        int k  = kc + kq;
        int ic = k >> 4;
        int ih = ih0 + ((k >> 2) & 3);
        const float* rp = ibase + ((size_t)ic*IH + ih)*IW;
        bool rowok = (unsigned)ih < (unsigned)IH;
        float sc = 0.f, sh = 0.f;
        if (BNIN) { sc = g_bnscale[ic]; sh = g_bnshift[ic]; }
        #pragma unroll
        for (int j = 0; j < 4; j++) {
            int iw = iw0 + j;
            float v = 0.f;
            if (rowok && (unsigned)iw < (unsigned)IW) {
                v = __ldg(rp + iw);
                if (BNIN) { v = v*sc + sh; v = v > 0.f ? v : 0.2f*v; }
            }
            pa[j] = v;
        }
    };
    auto loadB = [&](int kc) {
        pbv = *(const float4*)(wrow + kc);
    };
    auto stsA = [&](int buf) {
        #pragma unroll
        for (int j = 0; j < 4; j++) As[buf][kq+j][lm] = pa[j];
    };
    auto stsB = [&](int buf) {
        Bs[buf][bkq+0][boc] = pbv.x; Bs[buf][bkq+1][boc] = pbv.y;
        Bs[buf][bkq+2][boc] = pbv.z; Bs[buf][bkq+3][boc] = pbv.w;
    };

    loadA(k0); loadB(k0); stsA(0); stsB(0); __syncthreads();
    const int nch = Kchunk >> 4;
    for (int ch = 0; ch < nch; ch++) {
        int cur = ch & 1;
        if (ch + 1 < nch) { loadA(k0 + ((ch+1) << 4)); loadB(k0 + ((ch+1) << 4)); }
        #pragma unroll
        for (int k = 0; k < 16; k++) {
            float4 a = *(const float4*)&As[cur][k][tm];
            float4 b = *(const float4*)&Bs[cur][k][tn];
            acc[0][0] += a.x*b.x; acc[0][1] += a.x*b.y; acc[0][2] += a.x*b.z; acc[0][3] += a.x*b.w;
            acc[1][0] += a.y*b.x; acc[1][1] += a.y*b.y; acc[1][2] += a.y*b.z; acc[1][3] += a.y*b.w;
            acc[2][0] += a.z*b.x; acc[2][1] += a.z*b.y; acc[2][2] += a.z*b.z; acc[2][3] += a.z*b.w;
            acc[3][0] += a.w*b.x; acc[3][1] += a.w*b.y; acc[3][2] += a.w*b.z; acc[3][3] += a.w*b.w;
        }
        if (ch + 1 < nch) { stsA(cur ^ 1); stsB(cur ^ 1); __syncthreads(); }
    }

    #pragma unroll
    for (int i = 0; i < 4; i++) {
        int m = m0 + tm + i;
        float* op = pout + (size_t)m*NN + n0 + tn;
        op[0] = acc[i][0]; op[1] = acc[i][1]; op[2] = acc[i][2]; op[3] = acc[i][3];
    }
}

// ---------------- split-K reduce + bias -> NCHW ----------------
__global__ void redk_kernel(const float* __restrict__ part, const float* __restrict__ bias,
                            float* __restrict__ out, int MN, int log_nn, int KS, int log_ohw) {
    int NNm = (1 << log_nn) - 1;
    int OHWm = (1 << log_ohw) - 1;
    for (int idx = blockIdx.x*blockDim.x + threadIdx.x; idx < MN; idx += gridDim.x*blockDim.x) {
        int m = idx >> log_nn, n = idx & NNm;
        float s = 0.f;
        for (int z = 0; z < KS; z++) s += part[(size_t)z*MN + idx];
        s += bias[n];
        int ni = m >> log_ohw, rem = m & OHWm;
        out[((((size_t)ni << log_nn) + n) << log_ohw) + rem] = s;
    }
}

// ---------------- batchnorm stats (double accum) ----------------
__global__ void bn_reduce_kernel(const float* __restrict__ x, const float* __restrict__ g,
                                 const float* __restrict__ be, int N, int C, int S) {
    int c = blockIdx.x;
    double s = 0.0, s2 = 0.0;
    int M = N*S;
    for (int j = threadIdx.x; j < M; j += blockDim.x) {
        int n = j / S, sp = j % S;
        float v = x[((size_t)n*C + c)*S + sp];
        s += (double)v; s2 += (double)v*(double)v;
    }
    __shared__ double sh[256], sh2[256];
    sh[threadIdx.x] = s; sh2[threadIdx.x] = s2; __syncthreads();
    for (int st = 128; st > 0; st >>= 1) {
        if (threadIdx.x < st) { sh[threadIdx.x] += sh[threadIdx.x+st]; sh2[threadIdx.x] += sh2[threadIdx.x+st]; }
        __syncthreads();
    }
    if (threadIdx.x == 0) {
        double mean = sh[0] / M;
        double var  = sh2[0] / M - mean*mean;
        double isd  = 1.0 / sqrt(var + 1e-5);
        float sc = (float)((double)g[c] * isd);
        g_bnscale[c] = sc;
        g_bnshift[c] = be[c] - (float)(mean * (double)sc);
    }
}

// ---------------- head: bn4+lrelu+conv5 dot+softplus+mean ----------------
__global__ void head_kernel(const float* __restrict__ a4, const float* __restrict__ w5,
                            const float* __restrict__ b5, float* __restrict__ out) {
    int tid = threadIdx.x;            // 512
    int lane = tid & 31, warp = tid >> 5;   // 16 warps
    __shared__ float slog[64];
    for (int p = warp; p < NPATCH; p += 16) {
        const float* ap = a4 + (size_t)p*8192;
        float s = 0.f;
        for (int i = lane; i < 8192; i += 32) {
            int c = i >> 4;
            float v = ap[i]*g_bnscale[c] + g_bnshift[c];
            v = v > 0.f ? v : 0.2f*v;
            s += v * w5[i];
        }
        #pragma unroll
        for (int d = 16; d > 0; d >>= 1) s += __shfl_xor_sync(0xFFFFFFFFu, s, d);
        if (lane == 0) slog[p] = s + b5[0];
    }
    __syncthreads();
    if (tid < 64) {
        float x = -slog[tid];
        slog[tid] = fmaxf(x, 0.f) + log1pf(expf(-fabsf(x)));
    }
    __syncthreads();
    if (tid < 32) {
        float v = slog[tid] + slog[tid + 32];
        #pragma unroll
        for (int d = 16; d > 0; d >>= 1) v += __shfl_xor_sync(0xFFFFFFFFu, v, d);
        if (tid == 0) out[0] = v / 64.f;
    }
}

// ---------------- launcher ----------------
extern "C" void kernel_launch(void* const* d_in, const int* in_sizes, int n_in,
                              void* d_out, int out_size) {
    const float* pred     = (const float*)d_in[0];
    const float* source   = (const float*)d_in[1];
    const int*   rand_sel = (const int*)d_in[2];
    const float* w1 = (const float*)d_in[3];  const float* b1 = (const float*)d_in[4];
    const float* w2 = (const float*)d_in[5];  const float* b2 = (const float*)d_in[6];
    const float* g2 = (const float*)d_in[7];  const float* be2= (const float*)d_in[8];
    const float* w3 = (const float*)d_in[9];  const float* b3 = (const float*)d_in[10];
    const float* g3 = (const float*)d_in[11]; const float* be3= (const float*)d_in[12];
    const float* w4 = (const float*)d_in[13]; const float* b4 = (const float*)d_in[14];
    const float* g4 = (const float*)d_in[15]; const float* be4= (const float*)d_in[16];
    const float* w5 = (const float*)d_in[17]; const float* b5 = (const float*)d_in[18];
    float* out = (float*)d_out;

    float *patches, *a1, *a2, *a3, *a4, *part;
    cudaGetSymbolAddress((void**)&patches, g_patches);
    cudaGetSymbolAddress((void**)&a1, g_act1);
    cudaGetSymbolAddress((void**)&a2, g_act2);
    cudaGetSymbolAddress((void**)&a3, g_act3);
    cudaGetSymbolAddress((void**)&a4, g_act4);
    cudaGetSymbolAddress((void**)&part, g_part);

    // detector + pools
    hpool_det_kernel<<<dim3(HH, BB), 256>>>(source);
    vpool_kernel<<<dim3(WW/32, HH/64, BB), 256>>>();
    // fused top-k + coords (single launch)
    topk_all_kernel<<<BB, 1024>>>(rand_sel);
    // patch gather
    gather_kernel<<<(NPATCH*3*PS*PS + 255)/256, 256>>>(pred);
    // conv1 (64x64 tiles, bias+lrelu fused)
    conv1_kernel<<<1024, 256>>>(patches, w1, b1, a1);
    // conv2: M=16384, N=128, K=1024 (512 CTAs, no split-K)
    conv_gemm_kernel<64, 4, false><<<dim3(256, 2, 1), 256>>>(a1, w2, part, 1024, 1024);
    redk_kernel<<<2048, 256>>>(part, b2, a2, 16384*128, 7, 1, 8);
    bn_reduce_kernel<<<128, 256>>>(a2, g2, be2, NPATCH, 128, 16*16);
    // conv3: M=4096, N=256, K=2048, split-K=2 (512 CTAs), BN2+lrelu fused in
    conv_gemm_kernel<128, 3, true><<<dim3(64, 4, 2), 256>>>(a2, w3, part, 2048, 1024);
    redk_kernel<<<1024, 256>>>(part, b3, a3, 4096*256, 8, 2, 6);
    bn_reduce_kernel<<<256, 256>>>(a3, g3, be3, NPATCH, 256, 8*8);
    // conv4: M=1024, N=512, K=4096, split-K=4 (512 CTAs), BN3+lrelu fused in
    conv_gemm_kernel<256, 2, true><<<dim3(16, 8, 4), 256>>>(a3, w4, part, 4096, 1024);
    redk_kernel<<<512, 256>>>(part, b4, a4, 1024*512, 9, 4, 4);
    bn_reduce_kernel<<<512, 256>>>(a4, g4, be4, NPATCH, 512, 4*4);
    // head: bn4+lrelu+conv5+softplus+mean
    head_kernel<<<1, 512>>>(a4, w5, b5, out);
}

// round 7
// speedup vs baseline: 1.5179x; 1.2288x over previous
#include <cuda_runtime.h>
#include <cuda_bf16.h>
#include <cstdint>
#include <math.h>

#define BB 16
#define HH 768
#define WW 768
#define NPIX (HH*WW)
#define TOPK 100
#define NP 4
#define NPATCH (BB*NP)   // 64
#define PS 64            // patch size

// ---------------- scratch (static device globals) ----------------
__device__ float g_mask[BB*NPIX];
__device__ float g_tmp[BB*NPIX];
__device__ int g_listB[BB][32768];
__device__ int g_py[NPATCH], g_px[NPATCH];
__device__ float g_patches[NPATCH*3*PS*PS];
__device__ float g_act1[NPATCH*64*32*32];
__device__ float g_act2[NPATCH*128*16*16];
__device__ float g_act3[NPATCH*256*8*8];
__device__ float g_act4[NPATCH*512*4*4];
__device__ float g_part[4194304];
__device__ float g_bnscale[512], g_bnshift[512];

// ---------------- detector fused into 15-tap horizontal pool ---------------
__global__ void hpool_det_kernel(const float* __restrict__ src) {
    __shared__ float row[WW + 14];
    int y = blockIdx.x, b = blockIdx.y;
    const float* sb = src + ((size_t)b*3*HH + y)*WW;
    for (int i = threadIdx.x; i < WW + 14; i += blockDim.x) {
        int x = i - 7;
        float m = 0.f;
        if (x >= 0 && x < WW) {
            float r  = (sb[x]               + 1.f)*0.5f;
            float gg = (sb[(size_t)HH*WW + x]   + 1.f)*0.5f;
            float bl = (sb[(size_t)2*HH*WW + x] + 1.f)*0.5f;
            float br = 0.299f*r + 0.587f*gg + 0.114f*bl;
            float bm = 1.f/(1.f + expf(-20.f*(br - 0.65f)));
            float mx = fmaxf(r, fmaxf(gg, bl));
            float mn = fminf(r, fminf(gg, bl));
            float ls = 1.f/(1.f + expf(-20.f*(0.15f - (mx - mn))));
            m = bm*ls;
        }
        row[i] = m;
    }
    __syncthreads();
    float* op = g_tmp + ((size_t)b*HH + y)*WW;
    for (int x = threadIdx.x; x < WW; x += blockDim.x) {
        float s = 0.f;
        #pragma unroll
        for (int d = 0; d < 15; d++) s += row[x + d];
        op[x] = s;
    }
}

// ---------------- 15-tap vertical sum + /225 -> g_mask --------
__global__ void vpool_kernel() {
    __shared__ float tile[78][32];
    int c0 = blockIdx.x*32, r0 = blockIdx.y*64, b = blockIdx.z;
    const float* ip = g_tmp + (size_t)b*NPIX;
    for (int i = threadIdx.x; i < 78*32; i += blockDim.x) {
        int r = i >> 5, c = i & 31;
        int y = r0 + r - 7;
        tile[r][c] = (y >= 0 && y < HH) ? ip[(size_t)y*WW + c0 + c] : 0.f;
    }
    __syncthreads();
    float* op = g_mask + (size_t)b*NPIX;
    int c = threadIdx.x & 31;
    for (int rr = threadIdx.x >> 5; rr < 64; rr += blockDim.x >> 5) {
        float s = 0.f;
        #pragma unroll
        for (int d = 0; d < 15; d++) s += tile[rr + d][c];
        op[(size_t)(r0 + rr)*WW + c0 + c] = s / 225.0f;
    }
}

// ---------------- fused exact top-100 + coords: one block per image -------
__global__ __launch_bounds__(1024) void topk_all_kernel(const int* __restrict__ rand_sel) {
    const int b = blockIdx.x, tid = threadIdx.x;
    __shared__ unsigned hist[256];
    __shared__ unsigned s_prefix;
    __shared__ int s_K, s_cntA, s_cntB, s_bin, s_above, s_m;
    __shared__ unsigned long long A[128];
    __shared__ int stop[TOPK];
    __shared__ int smin[32];
    const float4* wp4 = (const float4*)(g_mask + (size_t)b*NPIX);
    if (tid == 0) { s_prefix = 0u; s_K = TOPK; s_cntA = 0; s_cntB = 0; }
    __syncthreads();

    for (int digit = 3; digit >= 0; digit--) {
        for (int i = tid; i < 256; i += 1024) hist[i] = 0u;
        __syncthreads();
        unsigned pref  = s_prefix;
        int      K     = s_K;
        unsigned hmask = (digit == 3) ? 0u : (0xFFFFFFFFu << ((digit + 1)*8));
        for (int i = tid; i < NPIX/4; i += 1024) {
            float4 v = wp4[i];
            unsigned k0 = __float_as_uint(v.x), k1 = __float_as_uint(v.y);
            unsigned k2 = __float_as_uint(v.z), k3 = __float_as_uint(v.w);
            if ((k0 & hmask) == (pref & hmask)) atomicAdd(&hist[(k0 >> (digit*8)) & 255u], 1u);
            if ((k1 & hmask) == (pref & hmask)) atomicAdd(&hist[(k1 >> (digit*8)) & 255u], 1u);
            if ((k2 & hmask) == (pref & hmask)) atomicAdd(&hist[(k2 >> (digit*8)) & 255u], 1u);
            if ((k3 & hmask) == (pref & hmask)) atomicAdd(&hist[(k3 >> (digit*8)) & 255u], 1u);
        }
        __syncthreads();
        if (tid < 256) {
            unsigned above = 0;
            for (int j = tid + 1; j < 256; j++) above += hist[j];
            if ((int)above < K && (int)(above + hist[tid]) >= K) { s_bin = tid; s_above = (int)above; }
        }
        __syncthreads();
        if (tid == 0) {
            s_prefix |= ((unsigned)s_bin) << (digit*8);
            s_K = s_K - s_above;
        }
        __syncthreads();
    }

    // collect
    unsigned T = s_prefix;
    for (int i = tid; i < NPIX/4; i += 1024) {
        float4 v = wp4[i];
        unsigned kk[4] = {__float_as_uint(v.x), __float_as_uint(v.y),
                          __float_as_uint(v.z), __float_as_uint(v.w)};
        #pragma unroll
        for (int j = 0; j < 4; j++) {
            unsigned key = kk[j];
            int idx = 4*i + j;
            if (key > T) {
                int p = atomicAdd(&s_cntA, 1);
                if (p < 128)
                    A[p] = ((unsigned long long)key << 32) | (unsigned)(0xFFFFFFFFu - (unsigned)idx);
            } else if (key == T) {
                int p = atomicAdd(&s_cntB, 1);
                if (p < 32768) g_listB[b][p] = idx;
            }
        }
    }
    __syncthreads();

    int G = min(s_cntA, 99);
    if (tid < G) {
        unsigned long long v = A[tid];
        int r = 0;
        for (int j = 0; j < G; j++) r += (A[j] > v) ? 1 : 0;
        stop[r] = (int)(0xFFFFFFFFu - (unsigned)(v & 0xFFFFFFFFu));
    }
    __syncthreads();

    int m  = TOPK - G;
    int nB = min(s_cntB, 32768);
    int lane = tid & 31, warp = tid >> 5;
    for (int k = 0; k < m; k++) {
        int lmin = 0x7FFFFFFF;
        for (int i = tid; i < nB; i += 1024) { int v = g_listB[b][i]; if (v < lmin) lmin = v; }
        #pragma unroll
        for (int s = 16; s > 0; s >>= 1) lmin = min(lmin, __shfl_xor_sync(0xFFFFFFFFu, lmin, s));
        if (lane == 0) smin[warp] = lmin;
        __syncthreads();
        if (warp == 0) {
            int v = smin[lane];
            #pragma unroll
            for (int s = 16; s > 0; s >>= 1) v = min(v, __shfl_xor_sync(0xFFFFFFFFu, v, s));
            if (lane == 0) { s_m = v; stop[G + k] = v; }
        }
        __syncthreads();
        int mv = s_m;
        for (int i = tid; i < nB; i += 1024) if (g_listB[b][i] == mv) g_listB[b][i] = 0x7FFFFFFF;
        __syncthreads();
    }

    if (tid < NP) {
        int r = rand_sel[b*NP + tid];
        int sel = stop[r];
        int y = sel / WW - PS/2; y = max(0, min(y, HH - PS));
        int x = sel % WW - PS/2; x = max(0, min(x, WW - PS));
        g_py[b*NP + tid] = y; g_px[b*NP + tid] = x;
    }
}

// ---------------- patch gather ----------------
__global__ void gather_kernel(const float* __restrict__ pred) {
    int idx = blockIdx.x*blockDim.x + threadIdx.x;
    const int total = NPATCH*3*PS*PS;
    if (idx >= total) return;
    int j = idx & 63; int t = idx >> 6;
    int i = t & 63;   t >>= 6;
    int c = t % 3;    int p = t / 3;
    int b = p >> 2;
    g_patches[idx] = pred[(((size_t)b*3 + c)*HH + g_py[p] + i)*WW + g_px[p] + j];
}

// ---------------- conv1: implicit GEMM 64x64, plain FFMA, K=48 ------------
__global__ __launch_bounds__(256) void conv1_kernel(
        const float* __restrict__ in, const float* __restrict__ w,
        const float* __restrict__ bias, float* __restrict__ out) {
    constexpr int IC = 3, LOG_OW = 5, OW = 32, OHW = OW*OW, IW = 64, IH = 64, K = 48;
    __shared__ __align__(16) float As[2][16][68];
    __shared__ __align__(16) float Bs[2][16][68];
    const int tid = threadIdx.x;
    const int m0  = blockIdx.x << 6;

    const int lm = tid >> 2;
    const int kq = (tid & 3) << 2;
    const int am   = m0 + lm;
    const int nimg = am >> (2*LOG_OW);
    const int arem = am & (OHW-1);
    const int ih0  = ((arem >> LOG_OW) << 1) - 1;
    const int iw0  = ((arem & (OW-1)) << 1) - 1;
    const float* ibase = in + (size_t)nimg*IC*IH*IW;

    const int boc = tid >> 2;
    const int bkq = (tid & 3) << 2;

    const int tm = (tid >> 4) << 2;
    const int tn = (tid & 15) << 2;

    float acc[4][4] = {};
    float pa[4]; float4 pbv;

    auto loadA = [&](int kc) {
        int k  = kc + kq;
        int ic = k >> 4;
        int ih = ih0 + ((k >> 2) & 3);
        const float* rp = ibase + ((size_t)ic*IH + ih)*IW;
        bool rowok = (unsigned)ih < (unsigned)IH;
        #pragma unroll
        for (int j = 0; j < 4; j++) {
            int iw = iw0 + j;
            pa[j] = (rowok && (unsigned)iw < (unsigned)IW) ? __ldg(rp + iw) : 0.f;
        }
    };
    auto loadB = [&](int kc) {
        pbv = *(const float4*)&w[(size_t)boc*K + kc + bkq];
    };
    auto stsA = [&](int buf) {
        #pragma unroll
        for (int j = 0; j < 4; j++) As[buf][kq+j][lm] = pa[j];
    };
    auto stsB = [&](int buf) {
        Bs[buf][bkq+0][boc] = pbv.x; Bs[buf][bkq+1][boc] = pbv.y;
        Bs[buf][bkq+2][boc] = pbv.z; Bs[buf][bkq+3][boc] = pbv.w;
    };

    loadA(0); loadB(0); stsA(0); stsB(0); __syncthreads();
    const int nch = K >> 4;
    for (int ch = 0; ch < nch; ch++) {
        int cur = ch & 1;
        if (ch + 1 < nch) { loadA((ch+1) << 4); loadB((ch+1) << 4); }
        #pragma unroll
        for (int k = 0; k < 16; k++) {
            float4 a = *(const float4*)&As[cur][k][tm];
            float4 b = *(const float4*)&Bs[cur][k][tn];
            acc[0][0] += a.x*b.x; acc[0][1] += a.x*b.y; acc[0][2] += a.x*b.z; acc[0][3] += a.x*b.w;
            acc[1][0] += a.y*b.x; acc[1][1] += a.y*b.y; acc[1][2] += a.y*b.z; acc[1][3] += a.y*b.w;
            acc[2][0] += a.z*b.x; acc[2][1] += a.z*b.y; acc[2][2] += a.z*b.z; acc[2][3] += a.z*b.w;
            acc[3][0] += a.w*b.x; acc[3][1] += a.w*b.y; acc[3][2] += a.w*b.z; acc[3][3] += a.w*b.w;
        }
        if (ch + 1 < nch) { stsA(cur ^ 1); stsB(cur ^ 1); __syncthreads(); }
    }

    const float4 bv = *(const float4*)&bias[tn];
    float b4[4] = {bv.x, bv.y, bv.z, bv.w};
    #pragma unroll
    for (int i = 0; i < 4; i++) {
        int m    = m0 + tm + i;
        int ni   = m >> (2*LOG_OW);
        int rem  = m & (OHW-1);
        float* op = out + ((size_t)ni*64 + tn)*OHW + rem;
        #pragma unroll
        for (int j = 0; j < 4; j++) {
            float v = acc[i][j] + b4[j];
            v = v > 0.f ? v : 0.2f*v;
            op[(size_t)j*OHW] = v;
        }
    }
}

// ---------------- bf16 split helpers ----------------
__device__ __forceinline__ void split2(float x, float y, unsigned& hi, unsigned& lo) {
    __nv_bfloat16 hx = __float2bfloat16_rn(x);
    __nv_bfloat16 hy = __float2bfloat16_rn(y);
    __nv_bfloat16 lx = __float2bfloat16_rn(x - __bfloat162float(hx));
    __nv_bfloat16 ly = __float2bfloat16_rn(y - __bfloat162float(hy));
    __nv_bfloat162 h = __nv_bfloat162(hx, hy);
    __nv_bfloat162 l = __nv_bfloat162(lx, ly);
    hi = *(unsigned*)&h; lo = *(unsigned*)&l;
}

__device__ __forceinline__ void mma_bf16(float* c, const unsigned* a, const unsigned* b) {
    asm volatile(
        "mma.sync.aligned.m16n8k16.row.col.f32.bf16.bf16.f32 "
        "{%0,%1,%2,%3}, {%4,%5,%6,%7}, {%8,%9}, {%0,%1,%2,%3};"
        : "+f"(c[0]), "+f"(c[1]), "+f"(c[2]), "+f"(c[3])
        : "r"(a[0]), "r"(a[1]), "r"(a[2]), "r"(a[3]), "r"(b[0]), "r"(b[1]));
}

// ---------------- conv2-4: implicit GEMM via bf16-split tensor core ------
// BM=BN=64, BK=32. 8 warps as 2(m)x4(n); warp tile 32x16; m16n8k16 mma.
// A = im2col(in) [M x K], B[n][k] = w[oc][k] (col-major for mma directly).
// x = hi + lo (bf16); x*y ~= hh + hl + lh, fp32 accumulate.
template<int IC, int LOG_OW, bool BNIN, bool DIRECT>
__global__ __launch_bounds__(256) void conv_mma_kernel(
        const float* __restrict__ in, const float* __restrict__ w,
        const float* __restrict__ bias, float* __restrict__ outp,
        int K, int Kchunk) {
    constexpr int OW = 1 << LOG_OW, OHW = OW*OW, IW = 2*OW, IH = IW;
    constexpr int STR = 40;   // bf16 elements per row (32 + 8 pad)
    __shared__ uint16_t Ah[2][64][STR], Al[2][64][STR];
    __shared__ uint16_t Bh[2][64][STR], Bl[2][64][STR];

    const int tid = threadIdx.x;
    const int m0  = blockIdx.x << 6;
    const int n0  = blockIdx.y << 6;
    const int NN  = gridDim.y << 6;
    const int MM  = gridDim.x << 6;
    const int k0  = blockIdx.z * Kchunk;
    float* pout = outp + (DIRECT ? 0 : (size_t)blockIdx.z * MM * NN);

    // global A mapping: row lm (0..63), k-range kq8..kq8+7
    const int lm  = tid >> 2;
    const int kq8 = (tid & 3) << 3;
    const int am   = m0 + lm;
    const int nimg = am >> (2*LOG_OW);
    const int arem = am & (OHW-1);
    const int ih0  = ((arem >> LOG_OW) << 1) - 1;
    const int iw0  = ((arem & (OW-1)) << 1) - 1;
    const float* ibase = in + (size_t)nimg*IC*IH*IW;

    // global B mapping: n-row brow, k-range bkq8..bkq8+7
    const int brow = tid >> 2;
    const int bkq8 = (tid & 3) << 3;
    const float* wrow = w + (size_t)(n0 + brow)*K;

    // warp layout
    const int wid  = tid >> 5, lane = tid & 31;
    const int wm   = (wid >> 2) << 5;        // 0 or 32
    const int wn   = (wid & 3) << 4;         // 0,16,32,48
    const int g    = lane >> 2;              // 0..7
    const int q    = lane & 3;               // 0..3

    float acc[2][2][4];
    #pragma unroll
    for (int i = 0; i < 2; i++)
        #pragma unroll
        for (int j = 0; j < 2; j++)
            #pragma unroll
            for (int e = 0; e < 4; e++) acc[i][j][e] = 0.f;

    float pa[8]; float4 pb0, pb1;

    auto loadA = [&](int kc) {
        int kbase = kc + kq8;
        int ic = kbase >> 4;
        float sc = 0.f, sh = 0.f;
        if (BNIN) { sc = g_bnscale[ic]; sh = g_bnshift[ic]; }
        #pragma unroll
        for (int grp = 0; grp < 2; grp++) {
            int k  = kbase + grp*4;
            int ih = ih0 + ((k >> 2) & 3);
            const float* rp = ibase + ((size_t)ic*IH + ih)*IW;
            bool rowok = (unsigned)ih < (unsigned)IH;
            #pragma unroll
            for (int j = 0; j < 4; j++) {
                int iw = iw0 + j;
                float v = 0.f;
                if (rowok && (unsigned)iw < (unsigned)IW) {
                    v = __ldg(rp + iw);
                    if (BNIN) { v = v*sc + sh; v = v > 0.f ? v : 0.2f*v; }
                }
                pa[grp*4 + j] = v;
            }
        }
    };
    auto loadB = [&](int kc) {
        pb0 = *(const float4*)(wrow + kc + bkq8);
        pb1 = *(const float4*)(wrow + kc + bkq8 + 4);
    };
    auto stsA = [&](int buf) {
        #pragma unroll
        for (int p = 0; p < 4; p++) {
            unsigned hi, lo;
            split2(pa[2*p], pa[2*p+1], hi, lo);
            *(unsigned*)&Ah[buf][lm][kq8 + 2*p] = hi;
            *(unsigned*)&Al[buf][lm][kq8 + 2*p] = lo;
        }
    };
    auto stsB = [&](int buf) {
        float bb[8] = {pb0.x, pb0.y, pb0.z, pb0.w, pb1.x, pb1.y, pb1.z, pb1.w};
        #pragma unroll
        for (int p = 0; p < 4; p++) {
            unsigned hi, lo;
            split2(bb[2*p], bb[2*p+1], hi, lo);
            *(unsigned*)&Bh[buf][brow][bkq8 + 2*p] = hi;
            *(unsigned*)&Bl[buf][brow][bkq8 + 2*p] = lo;
        }
    };

    loadA(k0); loadB(k0); stsA(0); stsB(0); __syncthreads();
    const int nch = Kchunk >> 5;
    for (int ch = 0; ch < nch; ch++) {
        int cur = ch & 1;
        if (ch + 1 < nch) { loadA(k0 + ((ch+1) << 5)); loadB(k0 + ((ch+1) << 5)); }
        #pragma unroll
        for (int step = 0; step < 2; step++) {
            const int ko = step*16 + q*2;   // element offset of this lane's k-pair
            unsigned ah[2][4], al[2][4], bh[2][2], bl[2][2];
            #pragma unroll
            for (int mf = 0; mf < 2; mf++) {
                int r = wm + mf*16 + g;
                ah[mf][0] = *(const unsigned*)&Ah[cur][r    ][ko];
                ah[mf][1] = *(const unsigned*)&Ah[cur][r + 8][ko];
                ah[mf][2] = *(const unsigned*)&Ah[cur][r    ][ko + 8];
                ah[mf][3] = *(const unsigned*)&Ah[cur][r + 8][ko + 8];
                al[mf][0] = *(const unsigned*)&Al[cur][r    ][ko];
                al[mf][1] = *(const unsigned*)&Al[cur][r + 8][ko];
                al[mf][2] = *(const unsigned*)&Al[cur][r    ][ko + 8];
                al[mf][3] = *(const unsigned*)&Al[cur][r + 8][ko + 8];
            }
            #pragma unroll
            for (int nf = 0; nf < 2; nf++) {
                int rb = wn + nf*8 + g;
                bh[nf][0] = *(const unsigned*)&Bh[cur][rb][ko];
                bh[nf][1] = *(const unsigned*)&Bh[cur][rb][ko + 8];
                bl[nf][0] = *(const unsigned*)&Bl[cur][rb][ko];
                bl[nf][1] = *(const unsigned*)&Bl[cur][rb][ko + 8];
            }
            #pragma unroll
            for (int mf = 0; mf < 2; mf++)
                #pragma unroll
                for (int nf = 0; nf < 2; nf++) {
                    mma_bf16(acc[mf][nf], ah[mf], bh[nf]);
                    mma_bf16(acc[mf][nf], ah[mf], bl[nf]);
                    mma_bf16(acc[mf][nf], al[mf], bh[nf]);
                }
        }
        if (ch + 1 < nch) { stsA(cur ^ 1); stsB(cur ^ 1); __syncthreads(); }
    }

    // epilogue
    #pragma unroll
    for (int mf = 0; mf < 2; mf++) {
        #pragma unroll
        for (int nf = 0; nf < 2; nf++) {
            int r0 = m0 + wm + mf*16 + g;
            int r1 = r0 + 8;
            int c0 = n0 + wn + nf*8 + q*2;
            if (DIRECT) {
                // write NCHW with bias (no split-K)
                float bv0 = bias[c0], bv1 = bias[c0 + 1];
                int ni0 = r0 >> (2*LOG_OW), rem0 = r0 & (OHW-1);
                int ni1 = r1 >> (2*LOG_OW), rem1 = r1 & (OHW-1);
                float* o00 = pout + (((size_t)ni0*NN + c0) << (2*LOG_OW)) + rem0;
                float* o10 = pout + (((size_t)ni1*NN + c0) << (2*LOG_OW)) + rem1;
                o00[0]            = acc[mf][nf][0] + bv0;
                o00[OHW]          = acc[mf][nf][1] + bv1;
                o10[0]            = acc[mf][nf][2] + bv0;
                o10[OHW]          = acc[mf][nf][3] + bv1;
            } else {
                *(float2*)(pout + (size_t)r0*NN + c0) = make_float2(acc[mf][nf][0], acc[mf][nf][1]);
                *(float2*)(pout + (size_t)r1*NN + c0) = make_float2(acc[mf][nf][2], acc[mf][nf][3]);
            }
        }
    }
}

// ---------------- split-K reduce + bias -> NCHW ----------------
__global__ void redk_kernel(const float* __restrict__ part, const float* __restrict__ bias,
                            float* __restrict__ out, int MN, int log_nn, int KS, int log_ohw) {
    int NNm = (1 << log_nn) - 1;
    int OHWm = (1 << log_ohw) - 1;
    for (int idx = blockIdx.x*blockDim.x + threadIdx.x; idx < MN; idx += gridDim.x*blockDim.x) {
        int m = idx >> log_nn, n = idx & NNm;
        float s = 0.f;
        for (int z = 0; z < KS; z++) s += part[(size_t)z*MN + idx];
        s += bias[n];
        int ni = m >> log_ohw, rem = m & OHWm;
        out[((((size_t)ni << log_nn) + n) << log_ohw) + rem] = s;
    }
}

// ---------------- batchnorm stats (double accum) ----------------
__global__ void bn_reduce_kernel(const float* __restrict__ x, const float* __restrict__ g,
                                 const float* __restrict__ be, int N, int C, int S) {
    int c = blockIdx.x;
    double s = 0.0, s2 = 0.0;
    int M = N*S;
    for (int j = threadIdx.x; j < M; j += blockDim.x) {
        int n = j / S, sp = j % S;
        float v = x[((size_t)n*C + c)*S + sp];
        s += (double)v; s2 += (double)v*(double)v;
    }
    __shared__ double sh[256], sh2[256];
    sh[threadIdx.x] = s; sh2[threadIdx.x] = s2; __syncthreads();
    for (int st = 128; st > 0; st >>= 1) {
        if (threadIdx.x < st) { sh[threadIdx.x] += sh[threadIdx.x+st]; sh2[threadIdx.x] += sh2[threadIdx.x+st]; }
        __syncthreads();
    }
    if (threadIdx.x == 0) {
        double mean = sh[0] / M;
        double var  = sh2[0] / M - mean*mean;
        double isd  = 1.0 / sqrt(var + 1e-5);
        float sc = (float)((double)g[c] * isd);
        g_bnscale[c] = sc;
        g_bnshift[c] = be[c] - (float)(mean * (double)sc);
    }
}

// ---------------- head: bn4+lrelu+conv5 dot+softplus+mean ----------------
__global__ void head_kernel(const float* __restrict__ a4, const float* __restrict__ w5,
                            const float* __restrict__ b5, float* __restrict__ out) {
    int tid = threadIdx.x;            // 512
    int lane = tid & 31, warp = tid >> 5;   // 16 warps
    __shared__ float slog[64];
    for (int p = warp; p < NPATCH; p += 16) {
        const float* ap = a4 + (size_t)p*8192;
        float s = 0.f;
        for (int i = lane; i < 8192; i += 32) {
            int c = i >> 4;
            float v = ap[i]*g_bnscale[c] + g_bnshift[c];
            v = v > 0.f ? v : 0.2f*v;
            s += v * w5[i];
        }
        #pragma unroll
        for (int d = 16; d > 0; d >>= 1) s += __shfl_xor_sync(0xFFFFFFFFu, s, d);
        if (lane == 0) slog[p] = s + b5[0];
    }
    __syncthreads();
    if (tid < 64) {
        float x = -slog[tid];
        slog[tid] = fmaxf(x, 0.f) + log1pf(expf(-fabsf(x)));
    }
    __syncthreads();
    if (tid < 32) {
        float v = slog[tid] + slog[tid + 32];
        #pragma unroll
        for (int d = 16; d > 0; d >>= 1) v += __shfl_xor_sync(0xFFFFFFFFu, v, d);
        if (tid == 0) out[0] = v / 64.f;
    }
}

// ---------------- launcher ----------------
extern "C" void kernel_launch(void* const* d_in, const int* in_sizes, int n_in,
                              void* d_out, int out_size) {
    const float* pred     = (const float*)d_in[0];
    const float* source   = (const float*)d_in[1];
    const int*   rand_sel = (const int*)d_in[2];
    const float* w1 = (const float*)d_in[3];  const float* b1 = (const float*)d_in[4];
    const float* w2 = (const float*)d_in[5];  const float* b2 = (const float*)d_in[6];
    const float* g2 = (const float*)d_in[7];  const float* be2= (const float*)d_in[8];
    const float* w3 = (const float*)d_in[9];  const float* b3 = (const float*)d_in[10];
    const float* g3 = (const float*)d_in[11]; const float* be3= (const float*)d_in[12];
    const float* w4 = (const float*)d_in[13]; const float* b4 = (const float*)d_in[14];
    const float* g4 = (const float*)d_in[15]; const float* be4= (const float*)d_in[16];
    const float* w5 = (const float*)d_in[17]; const float* b5 = (const float*)d_in[18];
    float* out = (float*)d_out;

    float *patches, *a1, *a2, *a3, *a4, *part;
    cudaGetSymbolAddress((void**)&patches, g_patches);
    cudaGetSymbolAddress((void**)&a1, g_act1);
    cudaGetSymbolAddress((void**)&a2, g_act2);
    cudaGetSymbolAddress((void**)&a3, g_act3);
    cudaGetSymbolAddress((void**)&a4, g_act4);
    cudaGetSymbolAddress((void**)&part, g_part);

    // detector + pools
    hpool_det_kernel<<<dim3(HH, BB), 256>>>(source);
    vpool_kernel<<<dim3(WW/32, HH/64, BB), 256>>>();
    // fused top-k + coords (single launch)
    topk_all_kernel<<<BB, 1024>>>(rand_sel);
    // patch gather
    gather_kernel<<<(NPATCH*3*PS*PS + 255)/256, 256>>>(pred);
    // conv1 (FFMA implicit GEMM, bias+lrelu fused)
    conv1_kernel<<<1024, 256>>>(patches, w1, b1, a1);
    // conv2: M=16384, N=128, K=1024 — bf16-split MMA, direct NCHW write+bias
    conv_mma_kernel<64, 4, false, true><<<dim3(256, 2, 1), 256>>>(a1, w2, b2, a2, 1024, 1024);
    bn_reduce_kernel<<<128, 256>>>(a2, g2, be2, NPATCH, 128, 16*16);
    // conv3: M=4096, N=256, K=2048, split-K=2, BN2+lrelu fused into input
    conv_mma_kernel<128, 3, true, false><<<dim3(64, 4, 2), 256>>>(a2, w3, b3, part, 2048, 1024);
    redk_kernel<<<1024, 256>>>(part, b3, a3, 4096*256, 8, 2, 6);
    bn_reduce_kernel<<<256, 256>>>(a3, g3, be3, NPATCH, 256, 8*8);
    // conv4: M=1024, N=512, K=4096, split-K=4, BN3+lrelu fused into input
    conv_mma_kernel<256, 2, true, false><<<dim3(16, 8, 4), 256>>>(a3, w4, b4, part, 4096, 1024);
    redk_kernel<<<512, 256>>>(part, b4, a4, 1024*512, 9, 4, 4);
    bn_reduce_kernel<<<512, 256>>>(a4, g4, be4, NPATCH, 512, 4*4);
    // head: bn4+lrelu+conv5+softplus+mean
    head_kernel<<<1, 512>>>(a4, w5, b5, out);
}

// round 9
// speedup vs baseline: 2.0980x; 1.3822x over previous
#include <cuda_runtime.h>
#include <cuda_bf16.h>
#include <cstdint>
#include <math.h>

#define BB 16
#define HH 768
#define WW 768
#define NPIX (HH*WW)
#define TOPK 100
#define NP 4
#define NPATCH (BB*NP)   // 64
#define PS 64            // patch size
#define CANDCAP 16384

// ---------------- scratch (static device globals) ----------------
__device__ float g_mask[BB*NPIX];
__device__ float g_tmp[BB*NPIX];
__device__ unsigned g_hist12[BB][4096];
__device__ unsigned g_T12[BB];
__device__ int g_candn[BB];
__device__ unsigned long long g_cand[BB][CANDCAP];
__device__ int g_py[NPATCH], g_px[NPATCH];
__device__ float g_patches[NPATCH*3*PS*PS];
__device__ float g_act1[NPATCH*64*32*32];
__device__ float g_act2[NPATCH*128*16*16];
__device__ float g_act3[NPATCH*256*8*8];
__device__ float g_act4[NPATCH*512*4*4];
__device__ float g_part[4194304];
__device__ float g_bnscale[512], g_bnshift[512];

// ---------------- detector fused into 15-tap horizontal pool ---------------
// also zeroes g_hist12 / g_candn (completes before vpool via stream order)
__global__ void hpool_det_kernel(const float* __restrict__ src) {
    if (blockIdx.y == 0 && blockIdx.x < 64) {
        int base = blockIdx.x * 1024;
        for (int i = threadIdx.x; i < 1024; i += 256)
            ((unsigned*)g_hist12)[base + i] = 0u;
    }
    if (blockIdx.y == 0 && blockIdx.x == 100 && threadIdx.x < BB)
        g_candn[threadIdx.x] = 0;

    __shared__ float row[WW + 14];
    int y = blockIdx.x, b = blockIdx.y;
    const float* sb = src + ((size_t)b*3*HH + y)*WW;
    for (int i = threadIdx.x; i < WW + 14; i += blockDim.x) {
        int x = i - 7;
        float m = 0.f;
        if (x >= 0 && x < WW) {
            float r  = (sb[x]               + 1.f)*0.5f;
            float gg = (sb[(size_t)HH*WW + x]   + 1.f)*0.5f;
            float bl = (sb[(size_t)2*HH*WW + x] + 1.f)*0.5f;
            float br = 0.299f*r + 0.587f*gg + 0.114f*bl;
            float bm = 1.f/(1.f + expf(-20.f*(br - 0.65f)));
            float mx = fmaxf(r, fmaxf(gg, bl));
            float mn = fminf(r, fminf(gg, bl));
            float ls = 1.f/(1.f + expf(-20.f*(0.15f - (mx - mn))));
            m = bm*ls;
        }
        row[i] = m;
    }
    __syncthreads();
    float* op = g_tmp + ((size_t)b*HH + y)*WW;
    for (int x = threadIdx.x; x < WW; x += blockDim.x) {
        float s = 0.f;
        #pragma unroll
        for (int d = 0; d < 15; d++) s += row[x + d];
        op[x] = s;
    }
}

// ---------------- 15-tap vertical sum + /225 -> g_mask, + 12-bit hist -----
__global__ void vpool_kernel() {
    __shared__ float tile[78][32];
    __shared__ unsigned shist[4096];
    int c0 = blockIdx.x*32, r0 = blockIdx.y*64, b = blockIdx.z;
    for (int i = threadIdx.x; i < 4096; i += blockDim.x) shist[i] = 0u;
    const float* ip = g_tmp + (size_t)b*NPIX;
    for (int i = threadIdx.x; i < 78*32; i += blockDim.x) {
        int r = i >> 5, c = i & 31;
        int y = r0 + r - 7;
        tile[r][c] = (y >= 0 && y < HH) ? ip[(size_t)y*WW + c0 + c] : 0.f;
    }
    __syncthreads();
    float* op = g_mask + (size_t)b*NPIX;
    int c = threadIdx.x & 31;
    for (int rr = threadIdx.x >> 5; rr < 64; rr += blockDim.x >> 5) {
        float s = 0.f;
        #pragma unroll
        for (int d = 0; d < 15; d++) s += tile[rr + d][c];
        float v = s / 225.0f;
        op[(size_t)(r0 + rr)*WW + c0 + c] = v;
        atomicAdd(&shist[__float_as_uint(v) >> 20], 1u);
    }
    __syncthreads();
    for (int i = threadIdx.x; i < 4096; i += blockDim.x) {
        unsigned cc = shist[i];
        if (cc) atomicAdd(&g_hist12[b][i], cc);
    }
}

// ---------------- resolve 12-bit threshold: 16 blocks ----------------
__global__ void topk_resolve_kernel() {
    int b = blockIdx.x, t = threadIdx.x;   // 256 threads
    __shared__ unsigned csum[257];
    __shared__ int s_c;
    unsigned s = 0;
    #pragma unroll
    for (int j = 0; j < 16; j++) s += g_hist12[b][t*16 + j];
    csum[t] = s;
    if (t == 0) csum[256] = 0;
    __syncthreads();
    for (int off = 1; off < 256; off <<= 1) {
        unsigned v = csum[t] + ((t + off < 256) ? csum[t + off] : 0u);
        __syncthreads();
        csum[t] = v;
        __syncthreads();
    }
    // csum[t] = count of values with bin >= t*16
    if (csum[t] >= TOPK && (t == 255 || csum[t + 1] < TOPK)) s_c = t;
    __syncthreads();
    if (t == 0) {
        int cch = s_c;
        unsigned running = (cch == 255) ? 0u : csum[cch + 1];
        unsigned T = (unsigned)(cch*16);
        for (int bin = cch*16 + 15; bin >= cch*16; bin--) {
            running += g_hist12[b][bin];
            if (running >= TOPK) { T = (unsigned)bin; break; }
        }
        g_T12[b] = T;
    }
}

// ---------------- collect candidates (one full scan, grid-wide) ----------
__global__ void topk_collect_kernel() {
    int b = blockIdx.y;
    unsigned T = g_T12[b];
    const float4* wp4 = (const float4*)(g_mask + (size_t)b*NPIX);
    for (int i = blockIdx.x*blockDim.x + threadIdx.x; i < NPIX/4; i += gridDim.x*blockDim.x) {
        float4 v = wp4[i];
        unsigned kk[4] = {__float_as_uint(v.x), __float_as_uint(v.y),
                          __float_as_uint(v.z), __float_as_uint(v.w)};
        #pragma unroll
        for (int j = 0; j < 4; j++) {
            if ((kk[j] >> 20) >= T) {
                int p = atomicAdd(&g_candn[b], 1);
                if (p < CANDCAP)
                    g_cand[b][p] = ((unsigned long long)kk[j] << 32)
                                 | (unsigned)(0xFFFFFFFFu - (unsigned)(4*i + j));
            }
        }
    }
}

// ---------------- exact top-100 by rank + coords ----------------
__global__ __launch_bounds__(1024) void topk_final_kernel(const int* __restrict__ rand_sel) {
    int b = blockIdx.x, tid = threadIdx.x;
    __shared__ unsigned long long ch[2048];
    __shared__ int stop[TOPK];
    int n = min(g_candn[b], CANDCAP);
    unsigned long long vi[16]; int ri[16]; int nc = 0;
    for (int i = tid; i < n; i += 1024) {
        if (nc < 16) { vi[nc] = g_cand[b][i]; ri[nc] = 0; nc++; }
    }
    for (int base = 0; base < n; base += 2048) {
        int len = min(2048, n - base);
        for (int j = tid; j < len; j += 1024) ch[j] = g_cand[b][base + j];
        __syncthreads();
        for (int cnd = 0; cnd < nc; cnd++) {
            unsigned long long v = vi[cnd]; int r = 0;
            for (int j = 0; j < len; j++) r += (ch[j] > v) ? 1 : 0;
            ri[cnd] += r;
        }
        __syncthreads();
    }
    for (int cnd = 0; cnd < nc; cnd++)
        if (ri[cnd] < TOPK)
            stop[ri[cnd]] = (int)(0xFFFFFFFFu - (unsigned)(vi[cnd] & 0xFFFFFFFFu));
    __syncthreads();
    if (tid < NP) {
        int r = rand_sel[b*NP + tid];
        int sel = stop[r];
        int y = sel / WW - PS/2; y = max(0, min(y, HH - PS));
        int x = sel % WW - PS/2; x = max(0, min(x, WW - PS));
        g_py[b*NP + tid] = y; g_px[b*NP + tid] = x;
    }
}

// ---------------- patch gather ----------------
__global__ void gather_kernel(const float* __restrict__ pred) {
    int idx = blockIdx.x*blockDim.x + threadIdx.x;
    const int total = NPATCH*3*PS*PS;
    if (idx >= total) return;
    int j = idx & 63; int t = idx >> 6;
    int i = t & 63;   t >>= 6;
    int c = t % 3;    int p = t / 3;
    int b = p >> 2;
    g_patches[idx] = pred[(((size_t)b*3 + c)*HH + g_py[p] + i)*WW + g_px[p] + j];
}

// ---------------- conv1: implicit GEMM 64x64, plain FFMA, K=48 ------------
__global__ __launch_bounds__(256) void conv1_kernel(
        const float* __restrict__ in, const float* __restrict__ w,
        const float* __restrict__ bias, float* __restrict__ out) {
    constexpr int IC = 3, LOG_OW = 5, OW = 32, OHW = OW*OW, IW = 64, IH = 64, K = 48;
    __shared__ __align__(16) float As[2][16][68];
    __shared__ __align__(16) float Bs[2][16][68];
    const int tid = threadIdx.x;
    const int m0  = blockIdx.x << 6;

    const int lm = tid >> 2;
    const int kq = (tid & 3) << 2;
    const int am   = m0 + lm;
    const int nimg = am >> (2*LOG_OW);
    const int arem = am & (OHW-1);
    const int ih0  = ((arem >> LOG_OW) << 1) - 1;
    const int iw0  = ((arem & (OW-1)) << 1) - 1;
    const float* ibase = in + (size_t)nimg*IC*IH*IW;

    const int boc = tid >> 2;
    const int bkq = (tid & 3) << 2;

    const int tm = (tid >> 4) << 2;
    const int tn = (tid & 15) << 2;

    float acc[4][4] = {};
    float pa[4]; float4 pbv;

    auto loadA = [&](int kc) {
        int k  = kc + kq;
        int ic = k >> 4;
        int ih = ih0 + ((k >> 2) & 3);
        const float* rp = ibase + ((size_t)ic*IH + ih)*IW;
        bool rowok = (unsigned)ih < (unsigned)IH;
        #pragma unroll
        for (int j = 0; j < 4; j++) {
            int iw = iw0 + j;
            pa[j] = (rowok && (unsigned)iw < (unsigned)IW) ? __ldg(rp + iw) : 0.f;
        }
    };
    auto loadB = [&](int kc) {
        pbv = *(const float4*)&w[(size_t)boc*K + kc + bkq];
    };
    auto stsA = [&](int buf) {
        #pragma unroll
        for (int j = 0; j < 4; j++) As[buf][kq+j][lm] = pa[j];
    };
    auto stsB = [&](int buf) {
        Bs[buf][bkq+0][boc] = pbv.x; Bs[buf][bkq+1][boc] = pbv.y;
        Bs[buf][bkq+2][boc] = pbv.z; Bs[buf][bkq+3][boc] = pbv.w;
    };

    loadA(0); loadB(0); stsA(0); stsB(0); __syncthreads();
    const int nch = K >> 4;
    for (int ch = 0; ch < nch; ch++) {
        int cur = ch & 1;
        if (ch + 1 < nch) { loadA((ch+1) << 4); loadB((ch+1) << 4); }
        #pragma unroll
        for (int k = 0; k < 16; k++) {
            float4 a = *(const float4*)&As[cur][k][tm];
            float4 b = *(const float4*)&Bs[cur][k][tn];
            acc[0][0] += a.x*b.x; acc[0][1] += a.x*b.y; acc[0][2] += a.x*b.z; acc[0][3] += a.x*b.w;
            acc[1][0] += a.y*b.x; acc[1][1] += a.y*b.y; acc[1][2] += a.y*b.z; acc[1][3] += a.y*b.w;
            acc[2][0] += a.z*b.x; acc[2][1] += a.z*b.y; acc[2][2] += a.z*b.z; acc[2][3] += a.z*b.w;
            acc[3][0] += a.w*b.x; acc[3][1] += a.w*b.y; acc[3][2] += a.w*b.z; acc[3][3] += a.w*b.w;
        }
        if (ch + 1 < nch) { stsA(cur ^ 1); stsB(cur ^ 1); __syncthreads(); }
    }

    const float4 bv = *(const float4*)&bias[tn];
    float b4[4] = {bv.x, bv.y, bv.z, bv.w};
    #pragma unroll
    for (int i = 0; i < 4; i++) {
        int m    = m0 + tm + i;
        int ni   = m >> (2*LOG_OW);
        int rem  = m & (OHW-1);
        float* op = out + ((size_t)ni*64 + tn)*OHW + rem;
        #pragma unroll
        for (int j = 0; j < 4; j++) {
            float v = acc[i][j] + b4[j];
            v = v > 0.f ? v : 0.2f*v;
            op[(size_t)j*OHW] = v;
        }
    }
}

// ---------------- bf16 split helpers ----------------
__device__ __forceinline__ void split2(float x, float y, unsigned& hi, unsigned& lo) {
    __nv_bfloat16 hx = __float2bfloat16_rn(x);
    __nv_bfloat16 hy = __float2bfloat16_rn(y);
    __nv_bfloat16 lx = __float2bfloat16_rn(x - __bfloat162float(hx));
    __nv_bfloat16 ly = __float2bfloat16_rn(y - __bfloat162float(hy));
    __nv_bfloat162 h = __nv_bfloat162(hx, hy);
    __nv_bfloat162 l = __nv_bfloat162(lx, ly);
    hi = *(unsigned*)&h; lo = *(unsigned*)&l;
}

__device__ __forceinline__ void mma_bf16(float* c, const unsigned* a, const unsigned* b) {
    asm volatile(
        "mma.sync.aligned.m16n8k16.row.col.f32.bf16.bf16.f32 "
        "{%0,%1,%2,%3}, {%4,%5,%6,%7}, {%8,%9}, {%0,%1,%2,%3};"
        : "+f"(c[0]), "+f"(c[1]), "+f"(c[2]), "+f"(c[3])
        : "r"(a[0]), "r"(a[1]), "r"(a[2]), "r"(a[3]), "r"(b[0]), "r"(b[1]));
}

// ---------------- conv2-4: bf16-split MMA, BM=64 BN=128 BK=32 -------------
// 8 warps 2(m)x4(n), warp tile 32x32. Split-K partials. BN+lrelu on input opt.
#define MSTR 40
#define SMEM_SZ (2*64*MSTR*2*2 + 2*128*MSTR*2*2)   // 61440
template<int IC, int LOG_OW, bool BNIN>
__global__ __launch_bounds__(256) void conv_mma_kernel(
        const float* __restrict__ in, const float* __restrict__ w,
        float* __restrict__ part, int K, int Kchunk) {
    constexpr int OW = 1 << LOG_OW, OHW = OW*OW, IW = 2*OW, IH = IW;
    extern __shared__ __align__(16) char dsm[];
    uint16_t* Ah = (uint16_t*)dsm;            // [2][64][MSTR]
    uint16_t* Al = Ah + 2*64*MSTR;
    uint16_t* Bh = Al + 2*64*MSTR;            // [2][128][MSTR]
    uint16_t* Bl = Bh + 2*128*MSTR;

    const int tid = threadIdx.x;
    const int m0  = blockIdx.x << 6;
    const int n0  = blockIdx.y << 7;
    const int NN  = gridDim.y << 7;
    const int MM  = gridDim.x << 6;
    const int k0  = blockIdx.z * Kchunk;
    float* pout = part + (size_t)blockIdx.z * MM * NN;

    // A mapping: row lm (0..63), k-range kq8..kq8+7
    const int lm  = tid >> 2;
    const int kq8 = (tid & 3) << 3;
    const int am   = m0 + lm;
    const int nimg = am >> (2*LOG_OW);
    const int arem = am & (OHW-1);
    const int ih0  = ((arem >> LOG_OW) << 1) - 1;
    const int iw0  = ((arem & (OW-1)) << 1) - 1;
    const float* ibase = in + (size_t)nimg*IC*IH*IW;

    // B mapping: row brow (0..127), k-range bk16..bk16+15
    const int brow = tid >> 1;
    const int bk16 = (tid & 1) << 4;
    const float* wrow = w + (size_t)(n0 + brow)*K;

    // warp layout: 2(m) x 4(n), warp tile 32x32
    const int wid  = tid >> 5, lane = tid & 31;
    const int wm   = (wid >> 2) << 5;        // 0,32
    const int wn   = (wid & 3) << 5;         // 0,32,64,96
    const int g    = lane >> 2;              // 0..7
    const int q    = lane & 3;               // 0..3

    float acc[2][4][4];
    #pragma unroll
    for (int i = 0; i < 2; i++)
        #pragma unroll
        for (int j = 0; j < 4; j++)
            #pragma unroll
            for (int e = 0; e < 4; e++) acc[i][j][e] = 0.f;

    float pa[8]; float4 pbv[4];

    auto loadA = [&](int kc) {
        int kbase = kc + kq8;
        int ic = kbase >> 4;
        float sc = 0.f, sh = 0.f;
        if (BNIN) { sc = g_bnscale[ic]; sh = g_bnshift[ic]; }
        #pragma unroll
        for (int grp = 0; grp < 2; grp++) {
            int k  = kbase + grp*4;
            int ih = ih0 + ((k >> 2) & 3);
            const float* rp = ibase + ((size_t)ic*IH + ih)*IW;
            bool rowok = (unsigned)ih < (unsigned)IH;
            #pragma unroll
            for (int j = 0; j < 4; j++) {
                int iw = iw0 + j;
                float v = 0.f;
                if (rowok && (unsigned)iw < (unsigned)IW) {
                    v = __ldg(rp + iw);
                    if (BNIN) { v = v*sc + sh; v = v > 0.f ? v : 0.2f*v; }
                }
                pa[grp*4 + j] = v;
            }
        }
    };
    auto loadB = [&](int kc) {
        #pragma unroll
        for (int j = 0; j < 4; j++)
            pbv[j] = *(const float4*)(wrow + kc + bk16 + 4*j);
    };
    auto stsA = [&](int buf) {
        #pragma unroll
        for (int p = 0; p < 4; p++) {
            unsigned hi, lo;
            split2(pa[2*p], pa[2*p+1], hi, lo);
            *(unsigned*)&Ah[(buf*64 + lm)*MSTR + kq8 + 2*p] = hi;
            *(unsigned*)&Al[(buf*64 + lm)*MSTR + kq8 + 2*p] = lo;
        }
    };
    auto stsB = [&](int buf) {
        float bb[16];
        #pragma unroll
        for (int j = 0; j < 4; j++) {
            bb[4*j+0] = pbv[j].x; bb[4*j+1] = pbv[j].y;
            bb[4*j+2] = pbv[j].z; bb[4*j+3] = pbv[j].w;
        }
        #pragma unroll
        for (int p = 0; p < 8; p++) {
            unsigned hi, lo;
            split2(bb[2*p], bb[2*p+1], hi, lo);
            *(unsigned*)&Bh[(buf*128 + brow)*MSTR + bk16 + 2*p] = hi;
            *(unsigned*)&Bl[(buf*128 + brow)*MSTR + bk16 + 2*p] = lo;
        }
    };

    loadA(k0); loadB(k0); stsA(0); stsB(0); __syncthreads();
    const int nch = Kchunk >> 5;
    for (int ch = 0; ch < nch; ch++) {
        int cur = ch & 1;
        if (ch + 1 < nch) { loadA(k0 + ((ch+1) << 5)); loadB(k0 + ((ch+1) << 5)); }
        #pragma unroll
        for (int step = 0; step < 2; step++) {
            const int ko = step*16 + q*2;
            unsigned ah[2][4], al[2][4], bh[4][2], bl[4][2];
            #pragma unroll
            for (int mf = 0; mf < 2; mf++) {
                int r = (cur*64 + wm + mf*16 + g)*MSTR;
                ah[mf][0] = *(const unsigned*)&Ah[r + ko];
                ah[mf][1] = *(const unsigned*)&Ah[r + 8*MSTR + ko];
                ah[mf][2] = *(const unsigned*)&Ah[r + ko + 8];
                ah[mf][3] = *(const unsigned*)&Ah[r + 8*MSTR + ko + 8];
                al[mf][0] = *(const unsigned*)&Al[r + ko];
                al[mf][1] = *(const unsigned*)&Al[r + 8*MSTR + ko];
                al[mf][2] = *(const unsigned*)&Al[r + ko + 8];
                al[mf][3] = *(const unsigned*)&Al[r + 8*MSTR + ko + 8];
            }
            #pragma unroll
            for (int nf = 0; nf < 4; nf++) {
                int rb = (cur*128 + wn + nf*8 + g)*MSTR;
                bh[nf][0] = *(const unsigned*)&Bh[rb + ko];
                bh[nf][1] = *(const unsigned*)&Bh[rb + ko + 8];
                bl[nf][0] = *(const unsigned*)&Bl[rb + ko];
                bl[nf][1] = *(const unsigned*)&Bl[rb + ko + 8];
            }
            #pragma unroll
            for (int mf = 0; mf < 2; mf++)
                #pragma unroll
                for (int nf = 0; nf < 4; nf++) {
                    mma_bf16(acc[mf][nf], ah[mf], bh[nf]);
                    mma_bf16(acc[mf][nf], ah[mf], bl[nf]);
                    mma_bf16(acc[mf][nf], al[mf], bh[nf]);
                }
        }
        if (ch + 1 < nch) { stsA(cur ^ 1); stsB(cur ^ 1); __syncthreads(); }
    }

    #pragma unroll
    for (int mf = 0; mf < 2; mf++) {
        #pragma unroll
        for (int nf = 0; nf < 4; nf++) {
            int r0 = m0 + wm + mf*16 + g;
            int r1 = r0 + 8;
            int c0 = n0 + wn + nf*8 + q*2;
            *(float2*)(pout + (size_t)r0*NN + c0) = make_float2(acc[mf][nf][0], acc[mf][nf][1]);
            *(float2*)(pout + (size_t)r1*NN + c0) = make_float2(acc[mf][nf][2], acc[mf][nf][3]);
        }
    }
}

// ---------------- split-K reduce + bias -> NCHW ----------------
__global__ void redk_kernel(const float* __restrict__ part, const float* __restrict__ bias,
                            float* __restrict__ out, int MN, int log_nn, int KS, int log_ohw) {
    int NNm = (1 << log_nn) - 1;
    int OHWm = (1 << log_ohw) - 1;
    for (int idx = blockIdx.x*blockDim.x + threadIdx.x; idx < MN; idx += gridDim.x*blockDim.x) {
        int m = idx >> log_nn, n = idx & NNm;
        float s = 0.f;
        for (int z = 0; z < KS; z++) s += part[(size_t)z*MN + idx];
        s += bias[n];
        int ni = m >> log_ohw, rem = m & OHWm;
        out[((((size_t)ni << log_nn) + n) << log_ohw) + rem] = s;
    }
}

// ---------------- batchnorm stats (double accum) ----------------
__global__ void bn_reduce_kernel(const float* __restrict__ x, const float* __restrict__ g,
                                 const float* __restrict__ be, int N, int C, int S) {
    int c = blockIdx.x;
    double s = 0.0, s2 = 0.0;
    int M = N*S;
    for (int j = threadIdx.x; j < M; j += blockDim.x) {
        int n = j / S, sp = j % S;
        float v = x[((size_t)n*C + c)*S + sp];
        s += (double)v; s2 += (double)v*(double)v;
    }
    __shared__ double sh[256], sh2[256];
    sh[threadIdx.x] = s; sh2[threadIdx.x] = s2; __syncthreads();
    for (int st = 128; st > 0; st >>= 1) {
        if (threadIdx.x < st) { sh[threadIdx.x] += sh[threadIdx.x+st]; sh2[threadIdx.x] += sh2[threadIdx.x+st]; }
        __syncthreads();
    }
    if (threadIdx.x == 0) {
        double mean = sh[0] / M;
        double var  = sh2[0] / M - mean*mean;
        double isd  = 1.0 / sqrt(var + 1e-5);
        float sc = (float)((double)g[c] * isd);
        g_bnscale[c] = sc;
        g_bnshift[c] = be[c] - (float)(mean * (double)sc);
    }
}

// ---------------- head: bn4+lrelu+conv5 dot+softplus+mean ----------------
__global__ void head_kernel(const float* __restrict__ a4, const float* __restrict__ w5,
                            const float* __restrict__ b5, float* __restrict__ out) {
    int tid = threadIdx.x;            // 512
    int lane = tid & 31, warp = tid >> 5;   // 16 warps
    __shared__ float slog[64];
    for (int p = warp; p < NPATCH; p += 16) {
        const float* ap = a4 + (size_t)p*8192;
        float s = 0.f;
        for (int i = lane; i < 8192; i += 32) {
            int c = i >> 4;
            float v = ap[i]*g_bnscale[c] + g_bnshift[c];
            v = v > 0.f ? v : 0.2f*v;
            s += v * w5[i];
        }
        #pragma unroll
        for (int d = 16; d > 0; d >>= 1) s += __shfl_xor_sync(0xFFFFFFFFu, s, d);
        if (lane == 0) slog[p] = s + b5[0];
    }
    __syncthreads();
    if (tid < 64) {
        float x = -slog[tid];
        slog[tid] = fmaxf(x, 0.f) + log1pf(expf(-fabsf(x)));
    }
    __syncthreads();
    if (tid < 32) {
        float v = slog[tid] + slog[tid + 32];
        #pragma unroll
        for (int d = 16; d > 0; d >>= 1) v += __shfl_xor_sync(0xFFFFFFFFu, v, d);
        if (tid == 0) out[0] = v / 64.f;
    }
}

// ---------------- launcher ----------------
extern "C" void kernel_launch(void* const* d_in, const int* in_sizes, int n_in,
                              void* d_out, int out_size) {
    const float* pred     = (const float*)d_in[0];
    const float* source   = (const float*)d_in[1];
    const int*   rand_sel = (const int*)d_in[2];
    const float* w1 = (const float*)d_in[3];  const float* b1 = (const float*)d_in[4];
    const float* w2 = (const float*)d_in[5];  const float* b2 = (const float*)d_in[6];
    const float* g2 = (const float*)d_in[7];  const float* be2= (const float*)d_in[8];
    const float* w3 = (const float*)d_in[9];  const float* b3 = (const float*)d_in[10];
    const float* g3 = (const float*)d_in[11]; const float* be3= (const float*)d_in[12];
    const float* w4 = (const float*)d_in[13]; const float* b4 = (const float*)d_in[14];
    const float* g4 = (const float*)d_in[15]; const float* be4= (const float*)d_in[16];
    const float* w5 = (const float*)d_in[17]; const float* b5 = (const float*)d_in[18];
    float* out = (float*)d_out;

    float *patches, *a1, *a2, *a3, *a4, *part;
    cudaGetSymbolAddress((void**)&patches, g_patches);
    cudaGetSymbolAddress((void**)&a1, g_act1);
    cudaGetSymbolAddress((void**)&a2, g_act2);
    cudaGetSymbolAddress((void**)&a3, g_act3);
    cudaGetSymbolAddress((void**)&a4, g_act4);
    cudaGetSymbolAddress((void**)&part, g_part);

    cudaFuncSetAttribute(conv_mma_kernel<64, 4, false>,
                         cudaFuncAttributeMaxDynamicSharedMemorySize, SMEM_SZ);
    cudaFuncSetAttribute(conv_mma_kernel<128, 3, true>,
                         cudaFuncAttributeMaxDynamicSharedMemorySize, SMEM_SZ);
    cudaFuncSetAttribute(conv_mma_kernel<256, 2, true>,
                         cudaFuncAttributeMaxDynamicSharedMemorySize, SMEM_SZ);

    // detector + pools (hist fused into vpool)
    hpool_det_kernel<<<dim3(HH, BB), 256>>>(source);
    vpool_kernel<<<dim3(WW/32, HH/64, BB), 256>>>();
    // topk: resolve threshold, collect candidates, exact rank
    topk_resolve_kernel<<<BB, 256>>>();
    topk_collect_kernel<<<dim3(48, BB), 256>>>();
    topk_final_kernel<<<BB, 1024>>>(rand_sel);
    // patch gather
    gather_kernel<<<(NPATCH*3*PS*PS + 255)/256, 256>>>(pred);
    // conv1 (FFMA implicit GEMM, bias+lrelu fused)
    conv1_kernel<<<1024, 256>>>(patches, w1, b1, a1);
    // conv2: M=16384, N=128, K=1024, split-K=2
    conv_mma_kernel<64, 4, false><<<dim3(256, 1, 2), 256, SMEM_SZ>>>(a1, w2, part, 1024, 512);
    redk_kernel<<<2048, 256>>>(part, b2, a2, 16384*128, 7, 2, 8);
    bn_reduce_kernel<<<128, 256>>>(a2, g2, be2, NPATCH, 128, 16*16);
    // conv3: M=4096, N=256, K=2048, split-K=4, BN2+lrelu fused into input
    conv_mma_kernel<128, 3, true><<<dim3(64, 2, 4), 256, SMEM_SZ>>>(a2, w3, part, 2048, 512);
    redk_kernel<<<1024, 256>>>(part, b3, a3, 4096*256, 8, 4, 6);
    bn_reduce_kernel<<<256, 256>>>(a3, g3, be3, NPATCH, 256, 8*8);
    // conv4: M=1024, N=512, K=4096, split-K=8, BN3+lrelu fused into input
    conv_mma_kernel<256, 2, true><<<dim3(16, 4, 8), 256, SMEM_SZ>>>(a3, w4, part, 4096, 512);
    redk_kernel<<<512, 256>>>(part, b4, a4, 1024*512, 9, 8, 4);
    bn_reduce_kernel<<<512, 256>>>(a4, g4, be4, NPATCH, 512, 4*4);
    // head: bn4+lrelu+conv5+softplus+mean
    head_kernel<<<1, 512>>>(a4, w5, b5, out);
}